// round 7
// baseline (speedup 1.0000x reference)
#include <cuda_runtime.h>
#include <cuda_bf16.h>
#include <math.h>
#include <stdint.h>

#define NN 131072
#define EE 262144
#define DD 128
#define RR 128
#define NB 148
#define GOUT 384

// ---- k_msgT smem layout (bytes) ----
#define MWLW 212                       // Wlo row stride (words)
#define MXW 216                        // X row stride (words); mod32=24 -> conflict-free B loads
#define MXROW (MXW * 4)                // 864
#define M_WLO 0                        // 128*212*4 = 108544
#define M_XHI 108544                   // 32*864 = 27648
#define M_XLO (M_XHI + 27648)          // 136192
#define M_STG (M_XLO + 27648)          // 163840 ; stage 32*132*4 = 16896
#define SMEM_MSG (M_STG + 16896)       // 180736
#define TEV 32

// ---- GRU smem layout ----
#define GWLW 68                        // Wlo row stride (words)
#define GXW 72                         // X row stride (words)
#define GSTG 388                       // stage row stride (floats)
#define GI_WLO 0                       // 384*68*4 = 104448
#define GI_XHI 104448                  // 32*72*4 = 9216
#define GI_XLO (GI_XHI + 9216)
#define GI_STG (GI_XLO + 9216)         // 122880 ; 32*388*4 = 49664
#define GI_SMEM (GI_STG + 49664)       // 172544
#define OUT_MRAW GI_SMEM               // 32*132*4 = 16896
#define OUT_SMEM (OUT_MRAW + 16896)    // 189440

// -------- device scratch --------
__device__ float g_sums[(size_t)NN * DD];
__device__ float g_cnt[NN];
__device__ int   g_tmax[NN];
__device__ float g_gi[(size_t)NN * GOUT];

// ================= helpers =================
__device__ __forceinline__ void mma16816(float* c,
                                         uint32_t a0, uint32_t a1, uint32_t a2, uint32_t a3,
                                         uint32_t b0, uint32_t b1) {
    asm volatile("mma.sync.aligned.m16n8k16.row.col.f32.bf16.bf16.f32 "
        "{%0,%1,%2,%3}, {%4,%5,%6,%7}, {%8,%9}, {%0,%1,%2,%3};"
        : "+f"(c[0]), "+f"(c[1]), "+f"(c[2]), "+f"(c[3])
        : "r"(a0), "r"(a1), "r"(a2), "r"(a3), "r"(b0), "r"(b1));
}
__device__ __forceinline__ uint32_t bfhi(float2 p) {
    __nv_bfloat162 h = __floats2bfloat162_rn(p.x, p.y);
    return *reinterpret_cast<uint32_t*>(&h);
}
__device__ __forceinline__ void bfsplit(float x, float y, uint32_t& hi, uint32_t& lo) {
    __nv_bfloat162 h = __floats2bfloat162_rn(x, y);
    float rx = x - __bfloat162float(h.x);
    float ry = y - __bfloat162float(h.y);
    __nv_bfloat162 l = __floats2bfloat162_rn(rx, ry);
    hi = *reinterpret_cast<uint32_t*>(&h);
    lo = *reinterpret_cast<uint32_t*>(&l);
}
__device__ __forceinline__ void split4(float4 v, uint2& hi, uint2& lo) {
    bfsplit(v.x, v.y, hi.x, lo.x);
    bfsplit(v.z, v.w, hi.y, lo.y);
}

// ============================================================
__global__ void k_init() {
    size_t i = (size_t)blockIdx.x * blockDim.x + threadIdx.x;
    size_t stride = (size_t)gridDim.x * blockDim.x;
    float4* s4 = (float4*)g_sums;
    for (size_t idx = i; idx < (size_t)NN * DD / 4; idx += stride)
        s4[idx] = make_float4(0.f, 0.f, 0.f, 0.f);
    for (size_t idx = i; idx < NN; idx += stride) { g_cnt[idx] = 0.f; g_tmax[idx] = 0; }
}

// ============================================================
// Message MLP: warp-specialized producer/consumer mma.sync pipeline.
// 384 threads: warps 0-7 = consumers (16 rows each, full K=416),
// warps 8-11 = producers (prefetch next 32-event tile regs->smem).
// ============================================================
__global__ void __launch_bounds__(384, 1) k_msgT(
    const float* __restrict__ mem, const float* __restrict__ raw,
    const float* __restrict__ tw,  const float* __restrict__ tb,
    const float* __restrict__ Ws,  const float* __restrict__ bs,
    const float* __restrict__ Wd,  const float* __restrict__ bd,
    const int* __restrict__ src, const int* __restrict__ dst,
    const int* __restrict__ tt,  const int* __restrict__ lu)
{
    extern __shared__ char smem[];
    uint32_t* wlo = (uint32_t*)(smem + M_WLO);
    uint32_t* xhi = (uint32_t*)(smem + M_XHI);
    uint32_t* xlo = (uint32_t*)(smem + M_XLO);
    float* stage  = (float*)(smem + M_STG);

    const int tid  = threadIdx.x;
    const int wid  = tid >> 5;
    const int lane = tid & 31;
    const int g    = lane >> 2;
    const int tig  = lane & 3;
    const bool cons = (wid < 8);
    const int side = (blockIdx.x >= NB);
    const int bid  = side ? blockIdx.x - NB : blockIdx.x;
    const float* W    = side ? Wd : Ws;
    const float* bias = side ? bd : bs;
    const int r0 = (wid & 7) * 16;
    const int STRIDE = NB * TEV;

    // ---- Wlo -> smem (all 384 threads) ----
    for (int idx = tid; idx < 128 * 104; idx += 384) {
        int r = idx / 104, c4 = idx - (idx / 104) * 104;
        float4 v = ((const float4*)W)[idx];
        uint2 hi, lo; split4(v, hi, lo);
        *(uint2*)((char*)smem + M_WLO + (size_t)r * (MWLW * 4) + c4 * 8) = lo;
        (void)hi;
    }

    // consumer state
    uint32_t whi[26][4];
    float b0r = 0.f, b1r = 0.f;
    if (cons) {
        const float* w0 = W + (size_t)(r0 + g) * 416 + 2 * tig;
        const float* w8 = w0 + 8 * 416;
        #pragma unroll
        for (int kk = 0; kk < 26; kk++) {
            whi[kk][0] = bfhi(*(const float2*)(w0 + kk * 16));
            whi[kk][1] = bfhi(*(const float2*)(w8 + kk * 16));
            whi[kk][2] = bfhi(*(const float2*)(w0 + kk * 16 + 8));
            whi[kk][3] = bfhi(*(const float2*)(w8 + kk * 16 + 8));
        }
        b0r = bias[r0 + g]; b1r = bias[r0 + g + 8];
    }

    // producer state
    const int ptid = tid - 256;               // 0..127 (producers)
    const int jt = ptid & 31;
    float twj = 0.f, tbj = 0.f;
    if (!cons) { twj = tw[jt]; tbj = tb[jt]; }
    float4 pf[24];
    float ptf[8];

#define PREFETCH(E0) do {                                                     \
    _Pragma("unroll")                                                         \
    for (int z = 0; z < 24; z++) {                                            \
        int idx = ptid + z * 128;                                             \
        int ev = idx / 96, c4 = idx - (idx / 96) * 96;                        \
        int e = (E0) + ev;                                                    \
        int vs = src[e], vd = dst[e];                                         \
        int a = side ? vd : vs, b = side ? vs : vd;                           \
        const float4* p; int f4;                                              \
        if (c4 < 32)      { p = (const float4*)(mem + (size_t)a * DD); f4 = c4; }      \
        else if (c4 < 64) { p = (const float4*)(mem + (size_t)b * DD); f4 = c4 - 32; } \
        else              { p = (const float4*)(raw + (size_t)e * RR); f4 = c4 - 64; } \
        pf[z] = p[f4];                                                        \
    }                                                                         \
    _Pragma("unroll")                                                         \
    for (int z = 0; z < 8; z++) {                                             \
        int ev = (ptid >> 5) + z * 4;                                         \
        int e = (E0) + ev;                                                    \
        int a = side ? dst[e] : src[e];                                       \
        float trel = __fsub_rn((float)tt[e], (float)lu[a]);                   \
        float arg  = __fadd_rn(__fmul_rn(trel, twj), tbj);                    \
        double d  = (double)arg;                                              \
        double kq = rint(d * 0.15915494309189535);                            \
        double rd = d - kq * 6.283185307179586;                               \
        ptf[z] = cosf((float)rd);                                             \
    }                                                                         \
} while (0)

#define STS_X() do {                                                          \
    _Pragma("unroll")                                                         \
    for (int z = 0; z < 24; z++) {                                            \
        int idx = ptid + z * 128;                                             \
        int ev = idx / 96, c4 = idx - (idx / 96) * 96;                        \
        uint2 hi, lo; split4(pf[z], hi, lo);                                  \
        int q = c4 & 3;                                                       \
        int w = (c4 >> 2) * 8 + (q >> 1) + (q & 1) * 4;                       \
        uint32_t* xh = xhi + ev * MXW + w;                                    \
        uint32_t* xl = xlo + ev * MXW + w;                                    \
        xh[0] = hi.x; xh[2] = hi.y;                                           \
        xl[0] = lo.x; xl[2] = lo.y;                                           \
    }                                                                         \
    _Pragma("unroll")                                                         \
    for (int z = 0; z < 8; z++) {                                             \
        int ev = (ptid >> 5) + z * 4;                                         \
        float c = ptf[z];                                                     \
        __nv_bfloat16 h = __float2bfloat16(c);                                \
        __nv_bfloat16 l = __float2bfloat16(c - __bfloat162float(h));          \
        int k = 384 + jt;                                                     \
        int p = k >> 1; int pi = p & 7; int kk = p >> 3;                      \
        int ws = kk * 8 + ((pi < 4) ? 2 * pi : 2 * (pi - 4) + 1);             \
        int byo = ev * MXROW + ws * 4 + (k & 1) * 2;                          \
        *(__nv_bfloat16*)((char*)smem + M_XHI + byo) = h;                     \
        *(__nv_bfloat16*)((char*)smem + M_XLO + byo) = l;                     \
    }                                                                         \
} while (0)

    if (!cons) PREFETCH(bid * TEV);
    __syncthreads();              // Wlo ready
    if (!cons) STS_X();
    __syncthreads();              // first X ready

    for (int e0 = bid * TEV; e0 < EE; e0 += STRIDE) {
        int e1 = e0 + STRIDE;
        if (cons) {
            // ---- mma: 3 sweeps over K=416 ----
            float acc[4][4];
            #pragma unroll
            for (int et = 0; et < 4; et++)
                acc[et][0] = acc[et][1] = acc[et][2] = acc[et][3] = 0.f;
            #pragma unroll
            for (int kk = 0; kk < 26; kk++) {
                uint32_t a0 = wlo[(r0 + g) * MWLW     + kk * 8 + tig];
                uint32_t a1 = wlo[(r0 + g + 8) * MWLW + kk * 8 + tig];
                uint32_t a2 = wlo[(r0 + g) * MWLW     + kk * 8 + tig + 4];
                uint32_t a3 = wlo[(r0 + g + 8) * MWLW + kk * 8 + tig + 4];
                #pragma unroll
                for (int et = 0; et < 4; et++) {
                    uint2 bh = *(const uint2*)(xhi + (et * 8 + g) * MXW + kk * 8 + 2 * tig);
                    uint2 bl = *(const uint2*)(xlo + (et * 8 + g) * MXW + kk * 8 + 2 * tig);
                    mma16816(acc[et], whi[kk][0], whi[kk][1], whi[kk][2], whi[kk][3], bh.x, bh.y);
                    mma16816(acc[et], a0, a1, a2, a3, bh.x, bh.y);
                    mma16816(acc[et], whi[kk][0], whi[kk][1], whi[kk][2], whi[kk][3], bl.x, bl.y);
                }
            }
            // ---- stage relu(msg + bias) ----
            #pragma unroll
            for (int et = 0; et < 4; et++) {
                int evl = et * 8 + 2 * tig;
                stage[evl * 132 + r0 + g]           = fmaxf(acc[et][0] + b0r, 0.f);
                stage[(evl + 1) * 132 + r0 + g]     = fmaxf(acc[et][1] + b0r, 0.f);
                stage[evl * 132 + r0 + g + 8]       = fmaxf(acc[et][2] + b1r, 0.f);
                stage[(evl + 1) * 132 + r0 + g + 8] = fmaxf(acc[et][3] + b1r, 0.f);
            }
        } else if (e1 < EE) {
            PREFETCH(e1);        // overlaps consumer mma
        }
        __syncthreads();         // X[e0] reads done; stage ready

        if (cons) {
            // ---- scatter atomics (overlaps producer STS) ----
            #pragma unroll
            for (int it = 0; it < 4; it++) {
                int idx = tid + it * 256;
                int ev = idx >> 5, q = idx & 31;
                int e = e0 + ev;
                int key = side ? dst[e] : src[e];
                float4 v = *(const float4*)(stage + ev * 132 + q * 4);
                atomicAdd((float4*)&g_sums[(size_t)key * DD + q * 4], v);
            }
            if (tid < TEV) {
                int e = e0 + tid;
                int key = side ? dst[e] : src[e];
                atomicAdd(&g_cnt[key], 1.0f);
                atomicMax(&g_tmax[key], tt[e]);
            }
        } else if (e1 < EE) {
            STS_X();
        }
        __syncthreads();         // next X ready / stage free
    }
#undef PREFETCH
#undef STS_X
}

// ============================================================
// gi = aggr @ W_ih^T + b_ih via mma.sync (256 thr, 8 warps x 48 rows, 32 nodes/tile)
// ============================================================
__global__ void __launch_bounds__(256, 1) k_gi2(
    const float* __restrict__ Wih, const float* __restrict__ bih)
{
    extern __shared__ char smem[];
    uint32_t* wlo = (uint32_t*)(smem + GI_WLO);
    uint32_t* xhi = (uint32_t*)(smem + GI_XHI);
    uint32_t* xlo = (uint32_t*)(smem + GI_XLO);
    float* stage  = (float*)(smem + GI_STG);

    const int tid = threadIdx.x;
    const int wid = tid >> 5;
    const int lane = tid & 31;
    const int g = lane >> 2, tig = lane & 3;

    for (int idx = tid; idx < GOUT * 32; idx += 256) {
        int r = idx >> 5, c4 = idx & 31;
        float4 v = ((const float4*)Wih)[idx];
        uint2 hi, lo; split4(v, hi, lo);
        *(uint2*)((char*)smem + GI_WLO + (size_t)r * (GWLW * 4) + c4 * 8) = lo;
        (void)hi;
    }
    uint32_t whi[3][8][4];
    float bv[3][2];
    #pragma unroll
    for (int rt = 0; rt < 3; rt++) {
        int r = wid * 48 + rt * 16 + g;
        const float* w0 = Wih + (size_t)r * 128 + 2 * tig;
        const float* w8 = w0 + 8 * 128;
        #pragma unroll
        for (int kk = 0; kk < 8; kk++) {
            whi[rt][kk][0] = bfhi(*(const float2*)(w0 + kk * 16));
            whi[rt][kk][1] = bfhi(*(const float2*)(w8 + kk * 16));
            whi[rt][kk][2] = bfhi(*(const float2*)(w0 + kk * 16 + 8));
            whi[rt][kk][3] = bfhi(*(const float2*)(w8 + kk * 16 + 8));
        }
        bv[rt][0] = bih[r]; bv[rt][1] = bih[r + 8];
    }
    __syncthreads();

    for (int n0 = blockIdx.x * 32; n0 < NN; n0 += gridDim.x * 32) {
        for (int idx = tid; idx < 32 * 32; idx += 256) {
            int n = idx >> 5, c4 = idx & 31;
            float4 v = ((const float4*)g_sums)[(size_t)(n0 + n) * 32 + c4];
            float inv = 1.0f / fmaxf(g_cnt[n0 + n], 1.0f);
            v.x *= inv; v.y *= inv; v.z *= inv; v.w *= inv;
            uint2 hi, lo; split4(v, hi, lo);
            int q = c4 & 3;
            int w = (c4 >> 2) * 8 + (q >> 1) + (q & 1) * 4;
            uint32_t* xh = xhi + n * GXW + w;
            uint32_t* xl = xlo + n * GXW + w;
            xh[0] = hi.x; xh[2] = hi.y;
            xl[0] = lo.x; xl[2] = lo.y;
        }
        __syncthreads();

        float acc[3][4][4];
        #pragma unroll
        for (int rt = 0; rt < 3; rt++)
            #pragma unroll
            for (int et = 0; et < 4; et++)
                acc[rt][et][0] = acc[rt][et][1] = acc[rt][et][2] = acc[rt][et][3] = 0.f;
        #pragma unroll
        for (int kk = 0; kk < 8; kk++) {
            uint2 bh[4], bl[4];
            #pragma unroll
            for (int et = 0; et < 4; et++) {
                bh[et] = *(const uint2*)(xhi + (et * 8 + g) * GXW + kk * 8 + 2 * tig);
                bl[et] = *(const uint2*)(xlo + (et * 8 + g) * GXW + kk * 8 + 2 * tig);
            }
            #pragma unroll
            for (int rt = 0; rt < 3; rt++) {
                int r = wid * 48 + rt * 16 + g;
                uint32_t a0 = wlo[r * GWLW + kk * 8 + tig];
                uint32_t a1 = wlo[(r + 8) * GWLW + kk * 8 + tig];
                uint32_t a2 = wlo[r * GWLW + kk * 8 + tig + 4];
                uint32_t a3 = wlo[(r + 8) * GWLW + kk * 8 + tig + 4];
                #pragma unroll
                for (int et = 0; et < 4; et++) {
                    mma16816(acc[rt][et], whi[rt][kk][0], whi[rt][kk][1], whi[rt][kk][2], whi[rt][kk][3], bh[et].x, bh[et].y);
                    mma16816(acc[rt][et], a0, a1, a2, a3, bh[et].x, bh[et].y);
                    mma16816(acc[rt][et], whi[rt][kk][0], whi[rt][kk][1], whi[rt][kk][2], whi[rt][kk][3], bl[et].x, bl[et].y);
                }
            }
        }
        #pragma unroll
        for (int rt = 0; rt < 3; rt++) {
            int r = wid * 48 + rt * 16 + g;
            #pragma unroll
            for (int et = 0; et < 4; et++) {
                int nl = et * 8 + 2 * tig;
                stage[nl * GSTG + r]           = acc[rt][et][0] + bv[rt][0];
                stage[(nl + 1) * GSTG + r]     = acc[rt][et][1] + bv[rt][0];
                stage[nl * GSTG + r + 8]       = acc[rt][et][2] + bv[rt][1];
                stage[(nl + 1) * GSTG + r + 8] = acc[rt][et][3] + bv[rt][1];
            }
        }
        __syncthreads();
        for (int idx = tid; idx < 32 * 96; idx += 256) {
            int n = idx / 96, c4 = idx - (idx / 96) * 96;
            ((float4*)g_gi)[(size_t)(n0 + n) * 96 + c4] =
                *(const float4*)(stage + n * GSTG + c4 * 4);
        }
        __syncthreads();
    }
}

// ============================================================
// gh = mem @ W_hh^T + b_hh via mma.sync, fused GRU combine -> out
// ============================================================
__global__ void __launch_bounds__(256, 1) k_out2(
    const float* __restrict__ Whh, const float* __restrict__ bhh,
    const float* __restrict__ mem, float* __restrict__ out)
{
    extern __shared__ char smem[];
    uint32_t* wlo = (uint32_t*)(smem + GI_WLO);
    uint32_t* xhi = (uint32_t*)(smem + GI_XHI);
    uint32_t* xlo = (uint32_t*)(smem + GI_XLO);
    float* stage  = (float*)(smem + GI_STG);
    float* mraw   = (float*)(smem + OUT_MRAW);

    const int tid = threadIdx.x;
    const int wid = tid >> 5;
    const int lane = tid & 31;
    const int g = lane >> 2, tig = lane & 3;

    for (int idx = tid; idx < GOUT * 32; idx += 256) {
        int r = idx >> 5, c4 = idx & 31;
        float4 v = ((const float4*)Whh)[idx];
        uint2 hi, lo; split4(v, hi, lo);
        *(uint2*)((char*)smem + GI_WLO + (size_t)r * (GWLW * 4) + c4 * 8) = lo;
        (void)hi;
    }
    uint32_t whi[3][8][4];
    float bv[3][2];
    #pragma unroll
    for (int rt = 0; rt < 3; rt++) {
        int r = wid * 48 + rt * 16 + g;
        const float* w0 = Whh + (size_t)r * 128 + 2 * tig;
        const float* w8 = w0 + 8 * 128;
        #pragma unroll
        for (int kk = 0; kk < 8; kk++) {
            whi[rt][kk][0] = bfhi(*(const float2*)(w0 + kk * 16));
            whi[rt][kk][1] = bfhi(*(const float2*)(w8 + kk * 16));
            whi[rt][kk][2] = bfhi(*(const float2*)(w0 + kk * 16 + 8));
            whi[rt][kk][3] = bfhi(*(const float2*)(w8 + kk * 16 + 8));
        }
        bv[rt][0] = bhh[r]; bv[rt][1] = bhh[r + 8];
    }
    __syncthreads();

    for (int n0 = blockIdx.x * 32; n0 < NN; n0 += gridDim.x * 32) {
        for (int idx = tid; idx < 32 * 32; idx += 256) {
            int n = idx >> 5, c4 = idx & 31;
            float4 v = ((const float4*)mem)[(size_t)(n0 + n) * 32 + c4];
            *(float4*)(mraw + n * 132 + c4 * 4) = v;
            uint2 hi, lo; split4(v, hi, lo);
            int q = c4 & 3;
            int w = (c4 >> 2) * 8 + (q >> 1) + (q & 1) * 4;
            uint32_t* xh = xhi + n * GXW + w;
            uint32_t* xl = xlo + n * GXW + w;
            xh[0] = hi.x; xh[2] = hi.y;
            xl[0] = lo.x; xl[2] = lo.y;
        }
        __syncthreads();

        float acc[3][4][4];
        #pragma unroll
        for (int rt = 0; rt < 3; rt++)
            #pragma unroll
            for (int et = 0; et < 4; et++)
                acc[rt][et][0] = acc[rt][et][1] = acc[rt][et][2] = acc[rt][et][3] = 0.f;
        #pragma unroll
        for (int kk = 0; kk < 8; kk++) {
            uint2 bh[4], bl[4];
            #pragma unroll
            for (int et = 0; et < 4; et++) {
                bh[et] = *(const uint2*)(xhi + (et * 8 + g) * GXW + kk * 8 + 2 * tig);
                bl[et] = *(const uint2*)(xlo + (et * 8 + g) * GXW + kk * 8 + 2 * tig);
            }
            #pragma unroll
            for (int rt = 0; rt < 3; rt++) {
                int r = wid * 48 + rt * 16 + g;
                uint32_t a0 = wlo[r * GWLW + kk * 8 + tig];
                uint32_t a1 = wlo[(r + 8) * GWLW + kk * 8 + tig];
                uint32_t a2 = wlo[r * GWLW + kk * 8 + tig + 4];
                uint32_t a3 = wlo[(r + 8) * GWLW + kk * 8 + tig + 4];
                #pragma unroll
                for (int et = 0; et < 4; et++) {
                    mma16816(acc[rt][et], whi[rt][kk][0], whi[rt][kk][1], whi[rt][kk][2], whi[rt][kk][3], bh[et].x, bh[et].y);
                    mma16816(acc[rt][et], a0, a1, a2, a3, bh[et].x, bh[et].y);
                    mma16816(acc[rt][et], whi[rt][kk][0], whi[rt][kk][1], whi[rt][kk][2], whi[rt][kk][3], bl[et].x, bl[et].y);
                }
            }
        }
        #pragma unroll
        for (int rt = 0; rt < 3; rt++) {
            int r = wid * 48 + rt * 16 + g;
            #pragma unroll
            for (int et = 0; et < 4; et++) {
                int nl = et * 8 + 2 * tig;
                stage[nl * GSTG + r]           = acc[rt][et][0] + bv[rt][0];
                stage[(nl + 1) * GSTG + r]     = acc[rt][et][1] + bv[rt][0];
                stage[nl * GSTG + r + 8]       = acc[rt][et][2] + bv[rt][1];
                stage[(nl + 1) * GSTG + r + 8] = acc[rt][et][3] + bv[rt][1];
            }
        }
        __syncthreads();

        // ---- fused GRU combine ----
        for (int idx = tid; idx < 32 * 32; idx += 256) {
            int n = idx >> 5, c4 = idx & 31;
            size_t gb = (size_t)(n0 + n) * GOUT + c4 * 4;
            float4 ir = *(const float4*)(g_gi + gb);
            float4 iz = *(const float4*)(g_gi + gb + 128);
            float4 in_ = *(const float4*)(g_gi + gb + 256);
            float4 hr = *(const float4*)(stage + n * GSTG + c4 * 4);
            float4 hz = *(const float4*)(stage + n * GSTG + 128 + c4 * 4);
            float4 hn = *(const float4*)(stage + n * GSTG + 256 + c4 * 4);
            float4 m = *(const float4*)(mraw + n * 132 + c4 * 4);
            float4 o;
            { float rg = 1.f/(1.f+expf(-(ir.x+hr.x))), zg = 1.f/(1.f+expf(-(iz.x+hz.x)));
              o.x = (1.f-zg)*tanhf(in_.x+rg*hn.x) + zg*m.x; }
            { float rg = 1.f/(1.f+expf(-(ir.y+hr.y))), zg = 1.f/(1.f+expf(-(iz.y+hz.y)));
              o.y = (1.f-zg)*tanhf(in_.y+rg*hn.y) + zg*m.y; }
            { float rg = 1.f/(1.f+expf(-(ir.z+hr.z))), zg = 1.f/(1.f+expf(-(iz.z+hz.z)));
              o.z = (1.f-zg)*tanhf(in_.z+rg*hn.z) + zg*m.z; }
            { float rg = 1.f/(1.f+expf(-(ir.w+hr.w))), zg = 1.f/(1.f+expf(-(iz.w+hz.w)));
              o.w = (1.f-zg)*tanhf(in_.w+rg*hn.w) + zg*m.w; }
            *(float4*)(out + (size_t)(n0 + n) * DD + c4 * 4) = o;
        }
        __syncthreads();
    }
}

// ============================================================
__global__ void k_lu(float* __restrict__ out) {
    int i = blockIdx.x * blockDim.x + threadIdx.x;
    if (i < NN)
        out[(size_t)NN * DD + i] = (g_cnt[i] > 0.f) ? (float)g_tmax[i] : 0.f;
}

// ============================================================
extern "C" void kernel_launch(void* const* d_in, const int* in_sizes, int n_in,
                              void* d_out, int out_size)
{
    const float* mem = (const float*)d_in[0];
    const float* raw = (const float*)d_in[1];
    const float* tw  = (const float*)d_in[2];
    const float* tb  = (const float*)d_in[3];
    const float* Ws  = (const float*)d_in[4];
    const float* bs  = (const float*)d_in[5];
    const float* Wd  = (const float*)d_in[6];
    const float* bd  = (const float*)d_in[7];
    const float* Wih = (const float*)d_in[8];
    const float* Whh = (const float*)d_in[9];
    const float* bih = (const float*)d_in[10];
    const float* bhh = (const float*)d_in[11];
    const int* src = (const int*)d_in[12];
    const int* dst = (const int*)d_in[13];
    const int* tt  = (const int*)d_in[14];
    const int* lu  = (const int*)d_in[15];
    float* out = (float*)d_out;

    cudaFuncSetAttribute(k_msgT, cudaFuncAttributeMaxDynamicSharedMemorySize, SMEM_MSG);
    cudaFuncSetAttribute(k_gi2,  cudaFuncAttributeMaxDynamicSharedMemorySize, GI_SMEM);
    cudaFuncSetAttribute(k_out2, cudaFuncAttributeMaxDynamicSharedMemorySize, OUT_SMEM);

    k_init<<<2048, 256>>>();
    k_msgT<<<2 * NB, 384, SMEM_MSG>>>(mem, raw, tw, tb, Ws, bs, Wd, bd, src, dst, tt, lu);
    k_gi2 <<<NB, 256, GI_SMEM>>>(Wih, bih);
    k_out2<<<NB, 256, OUT_SMEM>>>(Whh, bhh, mem, out);
    if (out_size >= NN * DD + NN)
        k_lu<<<(NN + 255) / 256, 256>>>(out);
}

// round 8
// speedup vs baseline: 1.7258x; 1.7258x over previous
#include <cuda_runtime.h>
#include <cuda_bf16.h>
#include <math.h>
#include <stdint.h>

#define NN 131072
#define EE 262144
#define DD 128
#define RR 128
#define NB 148
#define GOUT 384

// ---- k_msgT smem layout ----
#define MWLW 212                       // Wlo row stride words (mod32=20: A-rows conflict-free)
#define MXW 228                        // X row stride words (mod32=4: B-rows conflict-free)
#define MXROW (MXW * 4)                // 912 bytes
#define M_WLO 0                        // 128*212*4 = 108544
#define M_XHI 108544                   // 64*912 = 58368
#define M_XLO (M_XHI + 58368)          // 166912
#define SMEM_MSG (M_XLO + 58368)       // 225280
#define M_STG M_XHI                    // stage overlays xhi after mma (64*132*4=33792)

// ---- GRU smem layout (round-7 proven) ----
#define GWLW 68
#define GXW 72
#define GSTG 388
#define GI_WLO 0
#define GI_XHI 104448
#define GI_XLO (GI_XHI + 9216)
#define GI_STG (GI_XLO + 9216)
#define GI_SMEM (GI_STG + 49664)
#define OUT_MRAW GI_SMEM
#define OUT_SMEM (OUT_MRAW + 16896)

// -------- device scratch --------
__device__ float g_sums[(size_t)NN * DD];
__device__ float g_cnt[NN];
__device__ int   g_tmax[NN];
__device__ float g_gi[(size_t)NN * GOUT];

// ================= helpers =================
__device__ __forceinline__ void mma16816(float* c,
                                         uint32_t a0, uint32_t a1, uint32_t a2, uint32_t a3,
                                         uint32_t b0, uint32_t b1) {
    asm volatile("mma.sync.aligned.m16n8k16.row.col.f32.bf16.bf16.f32 "
        "{%0,%1,%2,%3}, {%4,%5,%6,%7}, {%8,%9}, {%0,%1,%2,%3};"
        : "+f"(c[0]), "+f"(c[1]), "+f"(c[2]), "+f"(c[3])
        : "r"(a0), "r"(a1), "r"(a2), "r"(a3), "r"(b0), "r"(b1));
}
__device__ __forceinline__ uint32_t bfhi(float2 p) {
    __nv_bfloat162 h = __floats2bfloat162_rn(p.x, p.y);
    return *reinterpret_cast<uint32_t*>(&h);
}
__device__ __forceinline__ void bfsplit(float x, float y, uint32_t& hi, uint32_t& lo) {
    __nv_bfloat162 h = __floats2bfloat162_rn(x, y);
    float rx = x - __bfloat162float(h.x);
    float ry = y - __bfloat162float(h.y);
    __nv_bfloat162 l = __floats2bfloat162_rn(rx, ry);
    hi = *reinterpret_cast<uint32_t*>(&h);
    lo = *reinterpret_cast<uint32_t*>(&l);
}
__device__ __forceinline__ void split4(float4 v, uint2& hi, uint2& lo) {
    bfsplit(v.x, v.y, hi.x, lo.x);
    bfsplit(v.z, v.w, hi.y, lo.y);
}

// ============================================================
__global__ void k_init() {
    size_t i = (size_t)blockIdx.x * blockDim.x + threadIdx.x;
    size_t stride = (size_t)gridDim.x * blockDim.x;
    float4* s4 = (float4*)g_sums;
    for (size_t idx = i; idx < (size_t)NN * DD / 4; idx += stride)
        s4[idx] = make_float4(0.f, 0.f, 0.f, 0.f);
    for (size_t idx = i; idx < NN; idx += stride) { g_cnt[idx] = 0.f; g_tmax[idx] = 0; }
}

// ============================================================
// Message MLP: mma.sync bf16 3-sweep, 512 threads / 16 warps.
// Warp pair (w, w+8): both own rows [(w&7)*16, +16); w does k-steps 0..12,
// w+8 does 13..25. Partials combined through the stage buffer.
// 64-event tiles, inline gather (round-6 proven structure).
// ============================================================
__global__ void __launch_bounds__(512, 1) k_msgT(
    const float* __restrict__ mem, const float* __restrict__ raw,
    const float* __restrict__ tw,  const float* __restrict__ tb,
    const float* __restrict__ Ws,  const float* __restrict__ bs,
    const float* __restrict__ Wd,  const float* __restrict__ bd,
    const int* __restrict__ src, const int* __restrict__ dst,
    const int* __restrict__ tt,  const int* __restrict__ lu)
{
    extern __shared__ char smem[];
    uint32_t* wlo = (uint32_t*)(smem + M_WLO);
    uint32_t* xhi = (uint32_t*)(smem + M_XHI);
    uint32_t* xlo = (uint32_t*)(smem + M_XLO);
    float* stage  = (float*)(smem + M_STG);

    const int tid  = threadIdx.x;
    const int wid  = tid >> 5;
    const int lane = tid & 31;
    const int g    = lane >> 2;
    const int tig  = lane & 3;
    const int half = wid >> 3;            // 0: kk 0..12, 1: kk 13..25
    const int ks   = half * 13;
    const int side = (blockIdx.x >= NB);
    const int bid  = side ? blockIdx.x - NB : blockIdx.x;
    const float* W    = side ? Wd : Ws;
    const float* bias = side ? bd : bs;
    const int r0 = (wid & 7) * 16;

    // ---- Wlo -> smem ----
    for (int idx = tid; idx < 128 * 104; idx += 512) {
        int r = idx / 104, c4 = idx - (idx / 104) * 104;
        float4 v = ((const float4*)W)[idx];
        uint2 hi, lo; split4(v, hi, lo);
        *(uint2*)((char*)smem + M_WLO + (size_t)r * (MWLW * 4) + c4 * 8) = lo;
        (void)hi;
    }

    // ---- Whi A-fragments (this warp's 13 k-steps) ----
    uint32_t whi[13][4];
    {
        const float* w0 = W + (size_t)(r0 + g) * 416 + ks * 16 + 2 * tig;
        const float* w8 = w0 + 8 * 416;
        #pragma unroll
        for (int kk = 0; kk < 13; kk++) {
            whi[kk][0] = bfhi(*(const float2*)(w0 + kk * 16));
            whi[kk][1] = bfhi(*(const float2*)(w8 + kk * 16));
            whi[kk][2] = bfhi(*(const float2*)(w0 + kk * 16 + 8));
            whi[kk][3] = bfhi(*(const float2*)(w8 + kk * 16 + 8));
        }
    }
    const float b0r = bias[r0 + g], b1r = bias[r0 + g + 8];
    const float twj = tw[lane], tbj = tb[lane];
    __syncthreads();

    for (int e0 = bid * 64; e0 < EE; e0 += NB * 64) {
        // ---- gather + split X (cols 0..383), 12 f4 per thread ----
        for (int idx = tid; idx < 64 * 96; idx += 512) {
            int ev = idx / 96, c4 = idx - (idx / 96) * 96;
            int e = e0 + ev;
            int vs = src[e], vd = dst[e];
            int a = side ? vd : vs, b = side ? vs : vd;
            const float4* p; int f4;
            if (c4 < 32)      { p = (const float4*)(mem + (size_t)a * DD); f4 = c4; }
            else if (c4 < 64) { p = (const float4*)(mem + (size_t)b * DD); f4 = c4 - 32; }
            else              { p = (const float4*)(raw + (size_t)e * RR); f4 = c4 - 64; }
            float4 v = p[f4];
            uint2 hi, lo; split4(v, hi, lo);
            int q = c4 & 3;
            int w = (c4 >> 2) * 8 + (q >> 1) + (q & 1) * 4;
            uint32_t* xh = xhi + ev * MXW + w;
            uint32_t* xl = xlo + ev * MXW + w;
            xh[0] = hi.x; xh[2] = hi.y;
            xl[0] = lo.x; xl[2] = lo.y;
        }
        // ---- time encoding (cols 384..415): 4 evs per thread ----
        #pragma unroll
        for (int z = 0; z < 4; z++) {
            int ev = wid + z * 16;
            int e = e0 + ev;
            int a = side ? dst[e] : src[e];
            float trel = __fsub_rn((float)tt[e], (float)lu[a]);
            float arg  = __fadd_rn(__fmul_rn(trel, twj), tbj);
            double d  = (double)arg;
            double kq = rint(d * 0.15915494309189535);
            double rd = d - kq * 6.283185307179586;
            float c = cosf((float)rd);
            __nv_bfloat16 h = __float2bfloat16(c);
            __nv_bfloat16 l = __float2bfloat16(c - __bfloat162float(h));
            int k  = 384 + lane;
            int p  = k >> 1;
            int pi = p & 7, kk = p >> 3;
            int w  = kk * 8 + ((pi < 4) ? 2 * pi : 2 * (pi - 4) + 1);
            int byo = ev * MXROW + w * 4 + (k & 1) * 2;
            *(__nv_bfloat16*)((char*)smem + M_XHI + byo) = h;
            *(__nv_bfloat16*)((char*)smem + M_XLO + byo) = l;
        }
        __syncthreads();

        // ---- mma: 3 sweeps over this warp's 13 k-steps ----
        float acc[8][4];
        #pragma unroll
        for (int et = 0; et < 8; et++)
            acc[et][0] = acc[et][1] = acc[et][2] = acc[et][3] = 0.f;
        #pragma unroll
        for (int kk = 0; kk < 13; kk++) {
            int kg = ks + kk;
            uint32_t a0 = wlo[(r0 + g) * MWLW     + kg * 8 + tig];
            uint32_t a1 = wlo[(r0 + g + 8) * MWLW + kg * 8 + tig];
            uint32_t a2 = wlo[(r0 + g) * MWLW     + kg * 8 + tig + 4];
            uint32_t a3 = wlo[(r0 + g + 8) * MWLW + kg * 8 + tig + 4];
            #pragma unroll
            for (int et = 0; et < 8; et++) {
                uint2 bh = *(const uint2*)(xhi + (et * 8 + g) * MXW + kg * 8 + 2 * tig);
                uint2 bl = *(const uint2*)(xlo + (et * 8 + g) * MXW + kg * 8 + 2 * tig);
                mma16816(acc[et], whi[kk][0], whi[kk][1], whi[kk][2], whi[kk][3], bh.x, bh.y);
                mma16816(acc[et], a0, a1, a2, a3, bh.x, bh.y);
                mma16816(acc[et], whi[kk][0], whi[kk][1], whi[kk][2], whi[kk][3], bl.x, bl.y);
            }
        }
        __syncthreads();   // xhi free -> stage overlays

        // ---- combine K halves through stage ----
        if (half) {
            #pragma unroll
            for (int et = 0; et < 8; et++) {
                int evl = et * 8 + 2 * tig;
                stage[evl * 132 + r0 + g]           = acc[et][0];
                stage[(evl + 1) * 132 + r0 + g]     = acc[et][1];
                stage[evl * 132 + r0 + g + 8]       = acc[et][2];
                stage[(evl + 1) * 132 + r0 + g + 8] = acc[et][3];
            }
        }
        __syncthreads();
        if (!half) {
            #pragma unroll
            for (int et = 0; et < 8; et++) {
                int evl = et * 8 + 2 * tig;
                float* s0 = stage + evl * 132;
                float* s1 = stage + (evl + 1) * 132;
                s0[r0 + g]     = fmaxf(acc[et][0] + s0[r0 + g]     + b0r, 0.f);
                s1[r0 + g]     = fmaxf(acc[et][1] + s1[r0 + g]     + b0r, 0.f);
                s0[r0 + g + 8] = fmaxf(acc[et][2] + s0[r0 + g + 8] + b1r, 0.f);
                s1[r0 + g + 8] = fmaxf(acc[et][3] + s1[r0 + g + 8] + b1r, 0.f);
            }
        }
        __syncthreads();

        // ---- scatter float4 atomics (4 per thread) ----
        #pragma unroll
        for (int it = 0; it < 4; it++) {
            int idx = tid + it * 512;
            int ev = idx >> 5, q = idx & 31;
            int e = e0 + ev;
            int key = side ? dst[e] : src[e];
            float4 v = *(const float4*)(stage + ev * 132 + q * 4);
            atomicAdd((float4*)&g_sums[(size_t)key * DD + q * 4], v);
        }
        if (tid < 64) {
            int e = e0 + tid;
            int key = side ? dst[e] : src[e];
            atomicAdd(&g_cnt[key], 1.0f);
            atomicMax(&g_tmax[key], tt[e]);
        }
        __syncthreads();
    }
}

// ============================================================
// gi = aggr @ W_ih^T + b_ih via mma.sync (round-7 proven)
// ============================================================
__global__ void __launch_bounds__(256, 1) k_gi2(
    const float* __restrict__ Wih, const float* __restrict__ bih)
{
    extern __shared__ char smem[];
    uint32_t* wlo = (uint32_t*)(smem + GI_WLO);
    uint32_t* xhi = (uint32_t*)(smem + GI_XHI);
    uint32_t* xlo = (uint32_t*)(smem + GI_XLO);
    float* stage  = (float*)(smem + GI_STG);

    const int tid = threadIdx.x;
    const int wid = tid >> 5;
    const int lane = tid & 31;
    const int g = lane >> 2, tig = lane & 3;

    for (int idx = tid; idx < GOUT * 32; idx += 256) {
        int r = idx >> 5, c4 = idx & 31;
        float4 v = ((const float4*)Wih)[idx];
        uint2 hi, lo; split4(v, hi, lo);
        *(uint2*)((char*)smem + GI_WLO + (size_t)r * (GWLW * 4) + c4 * 8) = lo;
        (void)hi;
    }
    uint32_t whi[3][8][4];
    float bv[3][2];
    #pragma unroll
    for (int rt = 0; rt < 3; rt++) {
        int r = wid * 48 + rt * 16 + g;
        const float* w0 = Wih + (size_t)r * 128 + 2 * tig;
        const float* w8 = w0 + 8 * 128;
        #pragma unroll
        for (int kk = 0; kk < 8; kk++) {
            whi[rt][kk][0] = bfhi(*(const float2*)(w0 + kk * 16));
            whi[rt][kk][1] = bfhi(*(const float2*)(w8 + kk * 16));
            whi[rt][kk][2] = bfhi(*(const float2*)(w0 + kk * 16 + 8));
            whi[rt][kk][3] = bfhi(*(const float2*)(w8 + kk * 16 + 8));
        }
        bv[rt][0] = bih[r]; bv[rt][1] = bih[r + 8];
    }
    __syncthreads();

    for (int n0 = blockIdx.x * 32; n0 < NN; n0 += gridDim.x * 32) {
        for (int idx = tid; idx < 32 * 32; idx += 256) {
            int n = idx >> 5, c4 = idx & 31;
            float4 v = ((const float4*)g_sums)[(size_t)(n0 + n) * 32 + c4];
            float inv = 1.0f / fmaxf(g_cnt[n0 + n], 1.0f);
            v.x *= inv; v.y *= inv; v.z *= inv; v.w *= inv;
            uint2 hi, lo; split4(v, hi, lo);
            int q = c4 & 3;
            int w = (c4 >> 2) * 8 + (q >> 1) + (q & 1) * 4;
            uint32_t* xh = xhi + n * GXW + w;
            uint32_t* xl = xlo + n * GXW + w;
            xh[0] = hi.x; xh[2] = hi.y;
            xl[0] = lo.x; xl[2] = lo.y;
        }
        __syncthreads();

        float acc[3][4][4];
        #pragma unroll
        for (int rt = 0; rt < 3; rt++)
            #pragma unroll
            for (int et = 0; et < 4; et++)
                acc[rt][et][0] = acc[rt][et][1] = acc[rt][et][2] = acc[rt][et][3] = 0.f;
        #pragma unroll
        for (int kk = 0; kk < 8; kk++) {
            uint2 bh[4], bl[4];
            #pragma unroll
            for (int et = 0; et < 4; et++) {
                bh[et] = *(const uint2*)(xhi + (et * 8 + g) * GXW + kk * 8 + 2 * tig);
                bl[et] = *(const uint2*)(xlo + (et * 8 + g) * GXW + kk * 8 + 2 * tig);
            }
            #pragma unroll
            for (int rt = 0; rt < 3; rt++) {
                int r = wid * 48 + rt * 16 + g;
                uint32_t a0 = wlo[r * GWLW + kk * 8 + tig];
                uint32_t a1 = wlo[(r + 8) * GWLW + kk * 8 + tig];
                uint32_t a2 = wlo[r * GWLW + kk * 8 + tig + 4];
                uint32_t a3 = wlo[(r + 8) * GWLW + kk * 8 + tig + 4];
                #pragma unroll
                for (int et = 0; et < 4; et++) {
                    mma16816(acc[rt][et], whi[rt][kk][0], whi[rt][kk][1], whi[rt][kk][2], whi[rt][kk][3], bh[et].x, bh[et].y);
                    mma16816(acc[rt][et], a0, a1, a2, a3, bh[et].x, bh[et].y);
                    mma16816(acc[rt][et], whi[rt][kk][0], whi[rt][kk][1], whi[rt][kk][2], whi[rt][kk][3], bl[et].x, bl[et].y);
                }
            }
        }
        #pragma unroll
        for (int rt = 0; rt < 3; rt++) {
            int r = wid * 48 + rt * 16 + g;
            #pragma unroll
            for (int et = 0; et < 4; et++) {
                int nl = et * 8 + 2 * tig;
                stage[nl * GSTG + r]           = acc[rt][et][0] + bv[rt][0];
                stage[(nl + 1) * GSTG + r]     = acc[rt][et][1] + bv[rt][0];
                stage[nl * GSTG + r + 8]       = acc[rt][et][2] + bv[rt][1];
                stage[(nl + 1) * GSTG + r + 8] = acc[rt][et][3] + bv[rt][1];
            }
        }
        __syncthreads();
        for (int idx = tid; idx < 32 * 96; idx += 256) {
            int n = idx / 96, c4 = idx - (idx / 96) * 96;
            ((float4*)g_gi)[(size_t)(n0 + n) * 96 + c4] =
                *(const float4*)(stage + n * GSTG + c4 * 4);
        }
        __syncthreads();
    }
}

// ============================================================
// gh = mem @ W_hh^T + b_hh via mma.sync + fused GRU combine (round-7 proven)
// ============================================================
__global__ void __launch_bounds__(256, 1) k_out2(
    const float* __restrict__ Whh, const float* __restrict__ bhh,
    const float* __restrict__ mem, float* __restrict__ out)
{
    extern __shared__ char smem[];
    uint32_t* wlo = (uint32_t*)(smem + GI_WLO);
    uint32_t* xhi = (uint32_t*)(smem + GI_XHI);
    uint32_t* xlo = (uint32_t*)(smem + GI_XLO);
    float* stage  = (float*)(smem + GI_STG);
    float* mraw   = (float*)(smem + OUT_MRAW);

    const int tid = threadIdx.x;
    const int wid = tid >> 5;
    const int lane = tid & 31;
    const int g = lane >> 2, tig = lane & 3;

    for (int idx = tid; idx < GOUT * 32; idx += 256) {
        int r = idx >> 5, c4 = idx & 31;
        float4 v = ((const float4*)Whh)[idx];
        uint2 hi, lo; split4(v, hi, lo);
        *(uint2*)((char*)smem + GI_WLO + (size_t)r * (GWLW * 4) + c4 * 8) = lo;
        (void)hi;
    }
    uint32_t whi[3][8][4];
    float bv[3][2];
    #pragma unroll
    for (int rt = 0; rt < 3; rt++) {
        int r = wid * 48 + rt * 16 + g;
        const float* w0 = Whh + (size_t)r * 128 + 2 * tig;
        const float* w8 = w0 + 8 * 128;
        #pragma unroll
        for (int kk = 0; kk < 8; kk++) {
            whi[rt][kk][0] = bfhi(*(const float2*)(w0 + kk * 16));
            whi[rt][kk][1] = bfhi(*(const float2*)(w8 + kk * 16));
            whi[rt][kk][2] = bfhi(*(const float2*)(w0 + kk * 16 + 8));
            whi[rt][kk][3] = bfhi(*(const float2*)(w8 + kk * 16 + 8));
        }
        bv[rt][0] = bhh[r]; bv[rt][1] = bhh[r + 8];
    }
    __syncthreads();

    for (int n0 = blockIdx.x * 32; n0 < NN; n0 += gridDim.x * 32) {
        for (int idx = tid; idx < 32 * 32; idx += 256) {
            int n = idx >> 5, c4 = idx & 31;
            float4 v = ((const float4*)mem)[(size_t)(n0 + n) * 32 + c4];
            *(float4*)(mraw + n * 132 + c4 * 4) = v;
            uint2 hi, lo; split4(v, hi, lo);
            int q = c4 & 3;
            int w = (c4 >> 2) * 8 + (q >> 1) + (q & 1) * 4;
            uint32_t* xh = xhi + n * GXW + w;
            uint32_t* xl = xlo + n * GXW + w;
            xh[0] = hi.x; xh[2] = hi.y;
            xl[0] = lo.x; xl[2] = lo.y;
        }
        __syncthreads();

        float acc[3][4][4];
        #pragma unroll
        for (int rt = 0; rt < 3; rt++)
            #pragma unroll
            for (int et = 0; et < 4; et++)
                acc[rt][et][0] = acc[rt][et][1] = acc[rt][et][2] = acc[rt][et][3] = 0.f;
        #pragma unroll
        for (int kk = 0; kk < 8; kk++) {
            uint2 bh[4], bl[4];
            #pragma unroll
            for (int et = 0; et < 4; et++) {
                bh[et] = *(const uint2*)(xhi + (et * 8 + g) * GXW + kk * 8 + 2 * tig);
                bl[et] = *(const uint2*)(xlo + (et * 8 + g) * GXW + kk * 8 + 2 * tig);
            }
            #pragma unroll
            for (int rt = 0; rt < 3; rt++) {
                int r = wid * 48 + rt * 16 + g;
                uint32_t a0 = wlo[r * GWLW + kk * 8 + tig];
                uint32_t a1 = wlo[(r + 8) * GWLW + kk * 8 + tig];
                uint32_t a2 = wlo[r * GWLW + kk * 8 + tig + 4];
                uint32_t a3 = wlo[(r + 8) * GWLW + kk * 8 + tig + 4];
                #pragma unroll
                for (int et = 0; et < 4; et++) {
                    mma16816(acc[rt][et], whi[rt][kk][0], whi[rt][kk][1], whi[rt][kk][2], whi[rt][kk][3], bh[et].x, bh[et].y);
                    mma16816(acc[rt][et], a0, a1, a2, a3, bh[et].x, bh[et].y);
                    mma16816(acc[rt][et], whi[rt][kk][0], whi[rt][kk][1], whi[rt][kk][2], whi[rt][kk][3], bl[et].x, bl[et].y);
                }
            }
        }
        #pragma unroll
        for (int rt = 0; rt < 3; rt++) {
            int r = wid * 48 + rt * 16 + g;
            #pragma unroll
            for (int et = 0; et < 4; et++) {
                int nl = et * 8 + 2 * tig;
                stage[nl * GSTG + r]           = acc[rt][et][0] + bv[rt][0];
                stage[(nl + 1) * GSTG + r]     = acc[rt][et][1] + bv[rt][0];
                stage[nl * GSTG + r + 8]       = acc[rt][et][2] + bv[rt][1];
                stage[(nl + 1) * GSTG + r + 8] = acc[rt][et][3] + bv[rt][1];
            }
        }
        __syncthreads();

        // ---- fused GRU combine ----
        for (int idx = tid; idx < 32 * 32; idx += 256) {
            int n = idx >> 5, c4 = idx & 31;
            size_t gb = (size_t)(n0 + n) * GOUT + c4 * 4;
            float4 ir = *(const float4*)(g_gi + gb);
            float4 iz = *(const float4*)(g_gi + gb + 128);
            float4 in_ = *(const float4*)(g_gi + gb + 256);
            float4 hr = *(const float4*)(stage + n * GSTG + c4 * 4);
            float4 hz = *(const float4*)(stage + n * GSTG + 128 + c4 * 4);
            float4 hn = *(const float4*)(stage + n * GSTG + 256 + c4 * 4);
            float4 m = *(const float4*)(mraw + n * 132 + c4 * 4);
            float4 o;
            { float rg = 1.f/(1.f+expf(-(ir.x+hr.x))), zg = 1.f/(1.f+expf(-(iz.x+hz.x)));
              o.x = (1.f-zg)*tanhf(in_.x+rg*hn.x) + zg*m.x; }
            { float rg = 1.f/(1.f+expf(-(ir.y+hr.y))), zg = 1.f/(1.f+expf(-(iz.y+hz.y)));
              o.y = (1.f-zg)*tanhf(in_.y+rg*hn.y) + zg*m.y; }
            { float rg = 1.f/(1.f+expf(-(ir.z+hr.z))), zg = 1.f/(1.f+expf(-(iz.z+hz.z)));
              o.z = (1.f-zg)*tanhf(in_.z+rg*hn.z) + zg*m.z; }
            { float rg = 1.f/(1.f+expf(-(ir.w+hr.w))), zg = 1.f/(1.f+expf(-(iz.w+hz.w)));
              o.w = (1.f-zg)*tanhf(in_.w+rg*hn.w) + zg*m.w; }
            *(float4*)(out + (size_t)(n0 + n) * DD + c4 * 4) = o;
        }
        __syncthreads();
    }
}

// ============================================================
__global__ void k_lu(float* __restrict__ out) {
    int i = blockIdx.x * blockDim.x + threadIdx.x;
    if (i < NN)
        out[(size_t)NN * DD + i] = (g_cnt[i] > 0.f) ? (float)g_tmax[i] : 0.f;
}

// ============================================================
extern "C" void kernel_launch(void* const* d_in, const int* in_sizes, int n_in,
                              void* d_out, int out_size)
{
    const float* mem = (const float*)d_in[0];
    const float* raw = (const float*)d_in[1];
    const float* tw  = (const float*)d_in[2];
    const float* tb  = (const float*)d_in[3];
    const float* Ws  = (const float*)d_in[4];
    const float* bs  = (const float*)d_in[5];
    const float* Wd  = (const float*)d_in[6];
    const float* bd  = (const float*)d_in[7];
    const float* Wih = (const float*)d_in[8];
    const float* Whh = (const float*)d_in[9];
    const float* bih = (const float*)d_in[10];
    const float* bhh = (const float*)d_in[11];
    const int* src = (const int*)d_in[12];
    const int* dst = (const int*)d_in[13];
    const int* tt  = (const int*)d_in[14];
    const int* lu  = (const int*)d_in[15];
    float* out = (float*)d_out;

    cudaFuncSetAttribute(k_msgT, cudaFuncAttributeMaxDynamicSharedMemorySize, SMEM_MSG);
    cudaFuncSetAttribute(k_gi2,  cudaFuncAttributeMaxDynamicSharedMemorySize, GI_SMEM);
    cudaFuncSetAttribute(k_out2, cudaFuncAttributeMaxDynamicSharedMemorySize, OUT_SMEM);

    k_init<<<2048, 256>>>();
    k_msgT<<<2 * NB, 512, SMEM_MSG>>>(mem, raw, tw, tb, Ws, bs, Wd, bd, src, dst, tt, lu);
    k_gi2 <<<NB, 256, GI_SMEM>>>(Wih, bih);
    k_out2<<<NB, 256, OUT_SMEM>>>(Whh, bhh, mem, out);
    if (out_size >= NN * DD + NN)
        k_lu<<<(NN + 255) / 256, 256>>>(out);
}

// round 9
// speedup vs baseline: 1.9143x; 1.1092x over previous
#include <cuda_runtime.h>
#include <cuda_bf16.h>
#include <math.h>
#include <stdint.h>

#define NN 131072
#define EE 262144
#define DD 128
#define RR 128
#define NB 148
#define GOUT 384

// 2*pi split: C1 = fp32(2*pi), C2 = 2*pi - C1
#define TWO_PI_C1 6.2831854820251465f
#define TWO_PI_C2 (-1.7484556e-7f)
#define INV_2PI   0.15915494309189535f

// ---- k_msgT smem layout ----
#define MWLW 212
#define MXW 228
#define MXROW (MXW * 4)
#define M_WLO 0
#define M_XHI 108544
#define M_XLO (M_XHI + 58368)
#define SMEM_MSG (M_XLO + 58368)
#define M_STG M_XHI

// ---- GRU smem layout ----
#define GWLW 68
#define GXW 72
#define GSTG 388
#define GI_WLO 0
#define GI_XHI 104448
#define GI_XLO (GI_XHI + 9216)
#define GI_STG (GI_XLO + 9216)
#define GI_SMEM (GI_STG + 49664)
#define OUT_MRAW GI_SMEM
#define OUT_SMEM (OUT_MRAW + 16896)

// -------- device scratch --------
__device__ float g_sums[(size_t)NN * DD];
__device__ float g_cnt[NN];
__device__ int   g_tmax[NN];
__device__ float g_gi[(size_t)NN * GOUT];

// ================= helpers =================
__device__ __forceinline__ void mma16816(float* c,
                                         uint32_t a0, uint32_t a1, uint32_t a2, uint32_t a3,
                                         uint32_t b0, uint32_t b1) {
    asm volatile("mma.sync.aligned.m16n8k16.row.col.f32.bf16.bf16.f32 "
        "{%0,%1,%2,%3}, {%4,%5,%6,%7}, {%8,%9}, {%0,%1,%2,%3};"
        : "+f"(c[0]), "+f"(c[1]), "+f"(c[2]), "+f"(c[3])
        : "r"(a0), "r"(a1), "r"(a2), "r"(a3), "r"(b0), "r"(b1));
}
__device__ __forceinline__ uint32_t bfhi(float2 p) {
    __nv_bfloat162 h = __floats2bfloat162_rn(p.x, p.y);
    return *reinterpret_cast<uint32_t*>(&h);
}
__device__ __forceinline__ void bfsplit(float x, float y, uint32_t& hi, uint32_t& lo) {
    __nv_bfloat162 h = __floats2bfloat162_rn(x, y);
    float rx = x - __bfloat162float(h.x);
    float ry = y - __bfloat162float(h.y);
    __nv_bfloat162 l = __floats2bfloat162_rn(rx, ry);
    hi = *reinterpret_cast<uint32_t*>(&h);
    lo = *reinterpret_cast<uint32_t*>(&l);
}
__device__ __forceinline__ void split4(float4 v, uint2& hi, uint2& lo) {
    bfsplit(v.x, v.y, hi.x, lo.x);
    bfsplit(v.z, v.w, hi.y, lo.y);
}
// cos of the exact fp32 arg, fp32-only Cody-Waite reduction
__device__ __forceinline__ float cos_exact(float arg) {
    float k = rintf(__fmul_rn(arg, INV_2PI));
    float r = fmaf(-k, TWO_PI_C1, arg);
    r = fmaf(-k, TWO_PI_C2, r);
    return cosf(r);
}

// ============================================================
__global__ void k_init() {
    size_t i = (size_t)blockIdx.x * blockDim.x + threadIdx.x;
    size_t stride = (size_t)gridDim.x * blockDim.x;
    float4* s4 = (float4*)g_sums;
    for (size_t idx = i; idx < (size_t)NN * DD / 4; idx += stride)
        s4[idx] = make_float4(0.f, 0.f, 0.f, 0.f);
    for (size_t idx = i; idx < NN; idx += stride) { g_cnt[idx] = 0.f; g_tmax[idx] = 0; }
}

// ============================================================
// Message MLP: mma.sync bf16 3-sweep, 512 threads / 16 warps, K-split pairs.
// ============================================================
__global__ void __launch_bounds__(512, 1) k_msgT(
    const float* __restrict__ mem, const float* __restrict__ raw,
    const float* __restrict__ tw,  const float* __restrict__ tb,
    const float* __restrict__ Ws,  const float* __restrict__ bs,
    const float* __restrict__ Wd,  const float* __restrict__ bd,
    const int* __restrict__ src, const int* __restrict__ dst,
    const int* __restrict__ tt,  const int* __restrict__ lu)
{
    extern __shared__ char smem[];
    uint32_t* wlo = (uint32_t*)(smem + M_WLO);
    uint32_t* xhi = (uint32_t*)(smem + M_XHI);
    uint32_t* xlo = (uint32_t*)(smem + M_XLO);
    float* stage  = (float*)(smem + M_STG);

    const int tid  = threadIdx.x;
    const int wid  = tid >> 5;
    const int lane = tid & 31;
    const int g    = lane >> 2;
    const int tig  = lane & 3;
    const int half = wid >> 3;
    const int ks   = half * 13;
    const int side = (blockIdx.x >= NB);
    const int bid  = side ? blockIdx.x - NB : blockIdx.x;
    const float* W    = side ? Wd : Ws;
    const float* bias = side ? bd : bs;
    const int r0 = (wid & 7) * 16;

    for (int idx = tid; idx < 128 * 104; idx += 512) {
        int r = idx / 104, c4 = idx - (idx / 104) * 104;
        float4 v = ((const float4*)W)[idx];
        uint2 hi, lo; split4(v, hi, lo);
        *(uint2*)((char*)smem + M_WLO + (size_t)r * (MWLW * 4) + c4 * 8) = lo;
        (void)hi;
    }

    uint32_t whi[13][4];
    {
        const float* w0 = W + (size_t)(r0 + g) * 416 + ks * 16 + 2 * tig;
        const float* w8 = w0 + 8 * 416;
        #pragma unroll
        for (int kk = 0; kk < 13; kk++) {
            whi[kk][0] = bfhi(*(const float2*)(w0 + kk * 16));
            whi[kk][1] = bfhi(*(const float2*)(w8 + kk * 16));
            whi[kk][2] = bfhi(*(const float2*)(w0 + kk * 16 + 8));
            whi[kk][3] = bfhi(*(const float2*)(w8 + kk * 16 + 8));
        }
    }
    const float b0r = bias[r0 + g], b1r = bias[r0 + g + 8];
    const float twj = tw[lane], tbj = tb[lane];
    __syncthreads();

    for (int e0 = bid * 64; e0 < EE; e0 += NB * 64) {
        // ---- gather + split X (cols 0..383) ----
        for (int idx = tid; idx < 64 * 96; idx += 512) {
            int ev = idx / 96, c4 = idx - (idx / 96) * 96;
            int e = e0 + ev;
            int vs = src[e], vd = dst[e];
            int a = side ? vd : vs, b = side ? vs : vd;
            const float4* p; int f4;
            if (c4 < 32)      { p = (const float4*)(mem + (size_t)a * DD); f4 = c4; }
            else if (c4 < 64) { p = (const float4*)(mem + (size_t)b * DD); f4 = c4 - 32; }
            else              { p = (const float4*)(raw + (size_t)e * RR); f4 = c4 - 64; }
            float4 v = p[f4];
            uint2 hi, lo; split4(v, hi, lo);
            int q = c4 & 3;
            int w = (c4 >> 2) * 8 + (q >> 1) + (q & 1) * 4;
            uint32_t* xh = xhi + ev * MXW + w;
            uint32_t* xl = xlo + ev * MXW + w;
            xh[0] = hi.x; xh[2] = hi.y;
            xl[0] = lo.x; xl[2] = lo.y;
        }
        // ---- time encoding (fp32-only reduction) ----
        #pragma unroll
        for (int z = 0; z < 4; z++) {
            int ev = wid + z * 16;
            int e = e0 + ev;
            int a = side ? dst[e] : src[e];
            float trel = __fsub_rn((float)tt[e], (float)lu[a]);
            float arg  = __fadd_rn(__fmul_rn(trel, twj), tbj);
            float c = cos_exact(arg);
            __nv_bfloat16 h = __float2bfloat16(c);
            __nv_bfloat16 l = __float2bfloat16(c - __bfloat162float(h));
            int k  = 384 + lane;
            int p  = k >> 1;
            int pi = p & 7, kk = p >> 3;
            int w  = kk * 8 + ((pi < 4) ? 2 * pi : 2 * (pi - 4) + 1);
            int byo = ev * MXROW + w * 4 + (k & 1) * 2;
            *(__nv_bfloat16*)((char*)smem + M_XHI + byo) = h;
            *(__nv_bfloat16*)((char*)smem + M_XLO + byo) = l;
        }
        __syncthreads();

        // ---- mma: 3 sweeps over this warp's 13 k-steps ----
        float acc[8][4];
        #pragma unroll
        for (int et = 0; et < 8; et++)
            acc[et][0] = acc[et][1] = acc[et][2] = acc[et][3] = 0.f;
        #pragma unroll
        for (int kk = 0; kk < 13; kk++) {
            int kg = ks + kk;
            uint32_t a0 = wlo[(r0 + g) * MWLW     + kg * 8 + tig];
            uint32_t a1 = wlo[(r0 + g + 8) * MWLW + kg * 8 + tig];
            uint32_t a2 = wlo[(r0 + g) * MWLW     + kg * 8 + tig + 4];
            uint32_t a3 = wlo[(r0 + g + 8) * MWLW + kg * 8 + tig + 4];
            #pragma unroll
            for (int et = 0; et < 8; et++) {
                uint2 bh = *(const uint2*)(xhi + (et * 8 + g) * MXW + kg * 8 + 2 * tig);
                uint2 bl = *(const uint2*)(xlo + (et * 8 + g) * MXW + kg * 8 + 2 * tig);
                mma16816(acc[et], whi[kk][0], whi[kk][1], whi[kk][2], whi[kk][3], bh.x, bh.y);
                mma16816(acc[et], a0, a1, a2, a3, bh.x, bh.y);
                mma16816(acc[et], whi[kk][0], whi[kk][1], whi[kk][2], whi[kk][3], bl.x, bl.y);
            }
        }
        __syncthreads();

        // ---- combine K halves through stage ----
        if (half) {
            #pragma unroll
            for (int et = 0; et < 8; et++) {
                int evl = et * 8 + 2 * tig;
                stage[evl * 132 + r0 + g]           = acc[et][0];
                stage[(evl + 1) * 132 + r0 + g]     = acc[et][1];
                stage[evl * 132 + r0 + g + 8]       = acc[et][2];
                stage[(evl + 1) * 132 + r0 + g + 8] = acc[et][3];
            }
        }
        __syncthreads();
        if (!half) {
            #pragma unroll
            for (int et = 0; et < 8; et++) {
                int evl = et * 8 + 2 * tig;
                float* s0 = stage + evl * 132;
                float* s1 = stage + (evl + 1) * 132;
                s0[r0 + g]     = fmaxf(acc[et][0] + s0[r0 + g]     + b0r, 0.f);
                s1[r0 + g]     = fmaxf(acc[et][1] + s1[r0 + g]     + b0r, 0.f);
                s0[r0 + g + 8] = fmaxf(acc[et][2] + s0[r0 + g + 8] + b1r, 0.f);
                s1[r0 + g + 8] = fmaxf(acc[et][3] + s1[r0 + g + 8] + b1r, 0.f);
            }
        }
        __syncthreads();

        // ---- scatter float4 atomics ----
        #pragma unroll
        for (int it = 0; it < 4; it++) {
            int idx = tid + it * 512;
            int ev = idx >> 5, q = idx & 31;
            int e = e0 + ev;
            int key = side ? dst[e] : src[e];
            float4 v = *(const float4*)(stage + ev * 132 + q * 4);
            atomicAdd((float4*)&g_sums[(size_t)key * DD + q * 4], v);
        }
        if (tid < 64) {
            int e = e0 + tid;
            int key = side ? dst[e] : src[e];
            atomicAdd(&g_cnt[key], 1.0f);
            atomicMax(&g_tmax[key], tt[e]);
        }
        __syncthreads();
    }
}

// ============================================================
// gi = aggr @ W_ih^T + b_ih via mma.sync (384 thr, 12 warps x 32 rows)
// ============================================================
__global__ void __launch_bounds__(384, 1) k_gi2(
    const float* __restrict__ Wih, const float* __restrict__ bih)
{
    extern __shared__ char smem[];
    uint32_t* wlo = (uint32_t*)(smem + GI_WLO);
    uint32_t* xhi = (uint32_t*)(smem + GI_XHI);
    uint32_t* xlo = (uint32_t*)(smem + GI_XLO);
    float* stage  = (float*)(smem + GI_STG);

    const int tid = threadIdx.x;
    const int wid = tid >> 5;
    const int lane = tid & 31;
    const int g = lane >> 2, tig = lane & 3;

    for (int idx = tid; idx < GOUT * 32; idx += 384) {
        int r = idx >> 5, c4 = idx & 31;
        float4 v = ((const float4*)Wih)[idx];
        uint2 hi, lo; split4(v, hi, lo);
        *(uint2*)((char*)smem + GI_WLO + (size_t)r * (GWLW * 4) + c4 * 8) = lo;
        (void)hi;
    }
    uint32_t whi[2][8][4];
    float bv[2][2];
    #pragma unroll
    for (int rt = 0; rt < 2; rt++) {
        int r = wid * 32 + rt * 16 + g;
        const float* w0 = Wih + (size_t)r * 128 + 2 * tig;
        const float* w8 = w0 + 8 * 128;
        #pragma unroll
        for (int kk = 0; kk < 8; kk++) {
            whi[rt][kk][0] = bfhi(*(const float2*)(w0 + kk * 16));
            whi[rt][kk][1] = bfhi(*(const float2*)(w8 + kk * 16));
            whi[rt][kk][2] = bfhi(*(const float2*)(w0 + kk * 16 + 8));
            whi[rt][kk][3] = bfhi(*(const float2*)(w8 + kk * 16 + 8));
        }
        bv[rt][0] = bih[r]; bv[rt][1] = bih[r + 8];
    }
    __syncthreads();

    for (int n0 = blockIdx.x * 32; n0 < NN; n0 += gridDim.x * 32) {
        for (int idx = tid; idx < 32 * 32; idx += 384) {
            int n = idx >> 5, c4 = idx & 31;
            float4 v = ((const float4*)g_sums)[(size_t)(n0 + n) * 32 + c4];
            float inv = 1.0f / fmaxf(g_cnt[n0 + n], 1.0f);
            v.x *= inv; v.y *= inv; v.z *= inv; v.w *= inv;
            uint2 hi, lo; split4(v, hi, lo);
            int q = c4 & 3;
            int w = (c4 >> 2) * 8 + (q >> 1) + (q & 1) * 4;
            uint32_t* xh = xhi + n * GXW + w;
            uint32_t* xl = xlo + n * GXW + w;
            xh[0] = hi.x; xh[2] = hi.y;
            xl[0] = lo.x; xl[2] = lo.y;
        }
        __syncthreads();

        float acc[2][4][4];
        #pragma unroll
        for (int rt = 0; rt < 2; rt++)
            #pragma unroll
            for (int et = 0; et < 4; et++)
                acc[rt][et][0] = acc[rt][et][1] = acc[rt][et][2] = acc[rt][et][3] = 0.f;
        #pragma unroll
        for (int kk = 0; kk < 8; kk++) {
            uint2 bh[4], bl[4];
            #pragma unroll
            for (int et = 0; et < 4; et++) {
                bh[et] = *(const uint2*)(xhi + (et * 8 + g) * GXW + kk * 8 + 2 * tig);
                bl[et] = *(const uint2*)(xlo + (et * 8 + g) * GXW + kk * 8 + 2 * tig);
            }
            #pragma unroll
            for (int rt = 0; rt < 2; rt++) {
                int r = wid * 32 + rt * 16 + g;
                uint32_t a0 = wlo[r * GWLW + kk * 8 + tig];
                uint32_t a1 = wlo[(r + 8) * GWLW + kk * 8 + tig];
                uint32_t a2 = wlo[r * GWLW + kk * 8 + tig + 4];
                uint32_t a3 = wlo[(r + 8) * GWLW + kk * 8 + tig + 4];
                #pragma unroll
                for (int et = 0; et < 4; et++) {
                    mma16816(acc[rt][et], whi[rt][kk][0], whi[rt][kk][1], whi[rt][kk][2], whi[rt][kk][3], bh[et].x, bh[et].y);
                    mma16816(acc[rt][et], a0, a1, a2, a3, bh[et].x, bh[et].y);
                    mma16816(acc[rt][et], whi[rt][kk][0], whi[rt][kk][1], whi[rt][kk][2], whi[rt][kk][3], bl[et].x, bl[et].y);
                }
            }
        }
        #pragma unroll
        for (int rt = 0; rt < 2; rt++) {
            int r = wid * 32 + rt * 16 + g;
            #pragma unroll
            for (int et = 0; et < 4; et++) {
                int nl = et * 8 + 2 * tig;
                stage[nl * GSTG + r]           = acc[rt][et][0] + bv[rt][0];
                stage[(nl + 1) * GSTG + r]     = acc[rt][et][1] + bv[rt][0];
                stage[nl * GSTG + r + 8]       = acc[rt][et][2] + bv[rt][1];
                stage[(nl + 1) * GSTG + r + 8] = acc[rt][et][3] + bv[rt][1];
            }
        }
        __syncthreads();
        for (int idx = tid; idx < 32 * 96; idx += 384) {
            int n = idx / 96, c4 = idx - (idx / 96) * 96;
            ((float4*)g_gi)[(size_t)(n0 + n) * 96 + c4] =
                *(const float4*)(stage + n * GSTG + c4 * 4);
        }
        __syncthreads();
    }
}

// ============================================================
// gh = mem @ W_hh^T + b_hh via mma.sync + fused GRU combine (384 thr)
// ============================================================
__global__ void __launch_bounds__(384, 1) k_out2(
    const float* __restrict__ Whh, const float* __restrict__ bhh,
    const float* __restrict__ mem, float* __restrict__ out)
{
    extern __shared__ char smem[];
    uint32_t* wlo = (uint32_t*)(smem + GI_WLO);
    uint32_t* xhi = (uint32_t*)(smem + GI_XHI);
    uint32_t* xlo = (uint32_t*)(smem + GI_XLO);
    float* stage  = (float*)(smem + GI_STG);
    float* mraw   = (float*)(smem + OUT_MRAW);

    const int tid = threadIdx.x;
    const int wid = tid >> 5;
    const int lane = tid & 31;
    const int g = lane >> 2, tig = lane & 3;

    for (int idx = tid; idx < GOUT * 32; idx += 384) {
        int r = idx >> 5, c4 = idx & 31;
        float4 v = ((const float4*)Whh)[idx];
        uint2 hi, lo; split4(v, hi, lo);
        *(uint2*)((char*)smem + GI_WLO + (size_t)r * (GWLW * 4) + c4 * 8) = lo;
        (void)hi;
    }
    uint32_t whi[2][8][4];
    float bv[2][2];
    #pragma unroll
    for (int rt = 0; rt < 2; rt++) {
        int r = wid * 32 + rt * 16 + g;
        const float* w0 = Whh + (size_t)r * 128 + 2 * tig;
        const float* w8 = w0 + 8 * 128;
        #pragma unroll
        for (int kk = 0; kk < 8; kk++) {
            whi[rt][kk][0] = bfhi(*(const float2*)(w0 + kk * 16));
            whi[rt][kk][1] = bfhi(*(const float2*)(w8 + kk * 16));
            whi[rt][kk][2] = bfhi(*(const float2*)(w0 + kk * 16 + 8));
            whi[rt][kk][3] = bfhi(*(const float2*)(w8 + kk * 16 + 8));
        }
        bv[rt][0] = bhh[r]; bv[rt][1] = bhh[r + 8];
    }
    __syncthreads();

    for (int n0 = blockIdx.x * 32; n0 < NN; n0 += gridDim.x * 32) {
        for (int idx = tid; idx < 32 * 32; idx += 384) {
            int n = idx >> 5, c4 = idx & 31;
            float4 v = ((const float4*)mem)[(size_t)(n0 + n) * 32 + c4];
            *(float4*)(mraw + n * 132 + c4 * 4) = v;
            uint2 hi, lo; split4(v, hi, lo);
            int q = c4 & 3;
            int w = (c4 >> 2) * 8 + (q >> 1) + (q & 1) * 4;
            uint32_t* xh = xhi + n * GXW + w;
            uint32_t* xl = xlo + n * GXW + w;
            xh[0] = hi.x; xh[2] = hi.y;
            xl[0] = lo.x; xl[2] = lo.y;
        }
        __syncthreads();

        float acc[2][4][4];
        #pragma unroll
        for (int rt = 0; rt < 2; rt++)
            #pragma unroll
            for (int et = 0; et < 4; et++)
                acc[rt][et][0] = acc[rt][et][1] = acc[rt][et][2] = acc[rt][et][3] = 0.f;
        #pragma unroll
        for (int kk = 0; kk < 8; kk++) {
            uint2 bh[4], bl[4];
            #pragma unroll
            for (int et = 0; et < 4; et++) {
                bh[et] = *(const uint2*)(xhi + (et * 8 + g) * GXW + kk * 8 + 2 * tig);
                bl[et] = *(const uint2*)(xlo + (et * 8 + g) * GXW + kk * 8 + 2 * tig);
            }
            #pragma unroll
            for (int rt = 0; rt < 2; rt++) {
                int r = wid * 32 + rt * 16 + g;
                uint32_t a0 = wlo[r * GWLW + kk * 8 + tig];
                uint32_t a1 = wlo[(r + 8) * GWLW + kk * 8 + tig];
                uint32_t a2 = wlo[r * GWLW + kk * 8 + tig + 4];
                uint32_t a3 = wlo[(r + 8) * GWLW + kk * 8 + tig + 4];
                #pragma unroll
                for (int et = 0; et < 4; et++) {
                    mma16816(acc[rt][et], whi[rt][kk][0], whi[rt][kk][1], whi[rt][kk][2], whi[rt][kk][3], bh[et].x, bh[et].y);
                    mma16816(acc[rt][et], a0, a1, a2, a3, bh[et].x, bh[et].y);
                    mma16816(acc[rt][et], whi[rt][kk][0], whi[rt][kk][1], whi[rt][kk][2], whi[rt][kk][3], bl[et].x, bl[et].y);
                }
            }
        }
        #pragma unroll
        for (int rt = 0; rt < 2; rt++) {
            int r = wid * 32 + rt * 16 + g;
            #pragma unroll
            for (int et = 0; et < 4; et++) {
                int nl = et * 8 + 2 * tig;
                stage[nl * GSTG + r]           = acc[rt][et][0] + bv[rt][0];
                stage[(nl + 1) * GSTG + r]     = acc[rt][et][1] + bv[rt][0];
                stage[nl * GSTG + r + 8]       = acc[rt][et][2] + bv[rt][1];
                stage[(nl + 1) * GSTG + r + 8] = acc[rt][et][3] + bv[rt][1];
            }
        }
        __syncthreads();

        for (int idx = tid; idx < 32 * 32; idx += 384) {
            int n = idx >> 5, c4 = idx & 31;
            size_t gb = (size_t)(n0 + n) * GOUT + c4 * 4;
            float4 ir = *(const float4*)(g_gi + gb);
            float4 iz = *(const float4*)(g_gi + gb + 128);
            float4 in_ = *(const float4*)(g_gi + gb + 256);
            float4 hr = *(const float4*)(stage + n * GSTG + c4 * 4);
            float4 hz = *(const float4*)(stage + n * GSTG + 128 + c4 * 4);
            float4 hn = *(const float4*)(stage + n * GSTG + 256 + c4 * 4);
            float4 m = *(const float4*)(mraw + n * 132 + c4 * 4);
            float4 o;
            { float rg = 1.f/(1.f+expf(-(ir.x+hr.x))), zg = 1.f/(1.f+expf(-(iz.x+hz.x)));
              o.x = (1.f-zg)*tanhf(in_.x+rg*hn.x) + zg*m.x; }
            { float rg = 1.f/(1.f+expf(-(ir.y+hr.y))), zg = 1.f/(1.f+expf(-(iz.y+hz.y)));
              o.y = (1.f-zg)*tanhf(in_.y+rg*hn.y) + zg*m.y; }
            { float rg = 1.f/(1.f+expf(-(ir.z+hr.z))), zg = 1.f/(1.f+expf(-(iz.z+hz.z)));
              o.z = (1.f-zg)*tanhf(in_.z+rg*hn.z) + zg*m.z; }
            { float rg = 1.f/(1.f+expf(-(ir.w+hr.w))), zg = 1.f/(1.f+expf(-(iz.w+hz.w)));
              o.w = (1.f-zg)*tanhf(in_.w+rg*hn.w) + zg*m.w; }
            *(float4*)(out + (size_t)(n0 + n) * DD + c4 * 4) = o;
        }
        __syncthreads();
    }
}

// ============================================================
__global__ void k_lu(float* __restrict__ out) {
    int i = blockIdx.x * blockDim.x + threadIdx.x;
    if (i < NN)
        out[(size_t)NN * DD + i] = (g_cnt[i] > 0.f) ? (float)g_tmax[i] : 0.f;
}

// ============================================================
extern "C" void kernel_launch(void* const* d_in, const int* in_sizes, int n_in,
                              void* d_out, int out_size)
{
    const float* mem = (const float*)d_in[0];
    const float* raw = (const float*)d_in[1];
    const float* tw  = (const float*)d_in[2];
    const float* tb  = (const float*)d_in[3];
    const float* Ws  = (const float*)d_in[4];
    const float* bs  = (const float*)d_in[5];
    const float* Wd  = (const float*)d_in[6];
    const float* bd  = (const float*)d_in[7];
    const float* Wih = (const float*)d_in[8];
    const float* Whh = (const float*)d_in[9];
    const float* bih = (const float*)d_in[10];
    const float* bhh = (const float*)d_in[11];
    const int* src = (const int*)d_in[12];
    const int* dst = (const int*)d_in[13];
    const int* tt  = (const int*)d_in[14];
    const int* lu  = (const int*)d_in[15];
    float* out = (float*)d_out;

    cudaFuncSetAttribute(k_msgT, cudaFuncAttributeMaxDynamicSharedMemorySize, SMEM_MSG);
    cudaFuncSetAttribute(k_gi2,  cudaFuncAttributeMaxDynamicSharedMemorySize, GI_SMEM);
    cudaFuncSetAttribute(k_out2, cudaFuncAttributeMaxDynamicSharedMemorySize, OUT_SMEM);

    k_init<<<2048, 256>>>();
    k_msgT<<<2 * NB, 512, SMEM_MSG>>>(mem, raw, tw, tb, Ws, bs, Wd, bd, src, dst, tt, lu);
    k_gi2 <<<NB, 384, GI_SMEM>>>(Wih, bih);
    k_out2<<<NB, 384, OUT_SMEM>>>(Whh, bhh, mem, out);
    if (out_size >= NN * DD + NN)
        k_lu<<<(NN + 255) / 256, 256>>>(out);
}

// round 10
// speedup vs baseline: 2.1870x; 1.1425x over previous
#include <cuda_runtime.h>
#include <cuda_bf16.h>
#include <cuda_fp16.h>
#include <math.h>
#include <stdint.h>

#define NN 131072
#define EE 262144
#define DD 128
#define RR 128
#define NB 148
#define GOUT 384

#define TWO_PI_C1 6.2831854820251465f
#define TWO_PI_C2 (-1.7484556e-7f)
#define INV_2PI   0.15915494309189535f

// ---- k_msgT smem layout: X only (Wlo lives in global g_wpk) ----
#define MXW 212                        // X row stride words (mod32=20 -> conflict-free)
#define MXROW (MXW * 4)                // 848 bytes
#define M_XHI 0                        // 64*848 = 54272
#define M_XLO 54272
#define SMEM_MSG (2 * 54272)           // 108544 -> 2 CTAs/SM
#define M_STG M_XHI                    // stage overlays xhi (64*132*4 = 33792)

// ---- GRU smem layout ----
#define GWLW 68
#define GXW 72
#define GSTG 388
#define GI_WLO 0
#define GI_XHI 104448
#define GI_XLO (GI_XHI + 9216)
#define GI_STG (GI_XLO + 9216)
#define GI_SMEM (GI_STG + 49664)
#define OUT_MRAW GI_SMEM
#define OUT_SMEM (OUT_MRAW + 16896)

// -------- device scratch --------
__device__ float g_sums[(size_t)NN * DD];
__device__ float g_cnt[NN];
__device__ int   g_tmax[NN];
__device__ uint2 g_gih[(size_t)NN * 96];            // gi in fp16 (96 uint2 = 384 half/node)
__device__ uint4 g_wpk[2 * 8 * 26 * 32];            // Wlo mma fragments, 213KB

// ================= helpers =================
__device__ __forceinline__ void mma16816(float* c,
                                         uint32_t a0, uint32_t a1, uint32_t a2, uint32_t a3,
                                         uint32_t b0, uint32_t b1) {
    asm volatile("mma.sync.aligned.m16n8k16.row.col.f32.bf16.bf16.f32 "
        "{%0,%1,%2,%3}, {%4,%5,%6,%7}, {%8,%9}, {%0,%1,%2,%3};"
        : "+f"(c[0]), "+f"(c[1]), "+f"(c[2]), "+f"(c[3])
        : "r"(a0), "r"(a1), "r"(a2), "r"(a3), "r"(b0), "r"(b1));
}
__device__ __forceinline__ uint32_t bfhi(float2 p) {
    __nv_bfloat162 h = __floats2bfloat162_rn(p.x, p.y);
    return *reinterpret_cast<uint32_t*>(&h);
}
__device__ __forceinline__ void bfsplit(float x, float y, uint32_t& hi, uint32_t& lo) {
    __nv_bfloat162 h = __floats2bfloat162_rn(x, y);
    float rx = x - __bfloat162float(h.x);
    float ry = y - __bfloat162float(h.y);
    __nv_bfloat162 l = __floats2bfloat162_rn(rx, ry);
    hi = *reinterpret_cast<uint32_t*>(&h);
    lo = *reinterpret_cast<uint32_t*>(&l);
}
__device__ __forceinline__ void split4(float4 v, uint2& hi, uint2& lo) {
    bfsplit(v.x, v.y, hi.x, lo.x);
    bfsplit(v.z, v.w, hi.y, lo.y);
}
__device__ __forceinline__ float cos_exact(float arg) {
    float k = rintf(__fmul_rn(arg, INV_2PI));
    float r = fmaf(-k, TWO_PI_C1, arg);
    r = fmaf(-k, TWO_PI_C2, r);
    return cosf(r);
}

// ============================================================
__global__ void k_init() {
    size_t i = (size_t)blockIdx.x * blockDim.x + threadIdx.x;
    size_t stride = (size_t)gridDim.x * blockDim.x;
    float4* s4 = (float4*)g_sums;
    for (size_t idx = i; idx < (size_t)NN * DD / 4; idx += stride)
        s4[idx] = make_float4(0.f, 0.f, 0.f, 0.f);
    for (size_t idx = i; idx < NN; idx += stride) { g_cnt[idx] = 0.f; g_tmax[idx] = 0; }
}

// ============================================================
// Prepack Wlo mma A-fragments: g_wpk[(side*208 + rg*26 + kg)*32 + lane]
//   = {lo(r0+g, c0..c0+1), lo(r0+g+8, c0..), lo(r0+g, c0+8..), lo(r0+g+8, c0+8..)}
//   r0 = rg*16, c0 = kg*16 + 2*tig.
// ============================================================
__global__ void k_pack(const float* __restrict__ Ws, const float* __restrict__ Wd) {
    int lane = threadIdx.x;
    int b = blockIdx.x;                 // 0..415
    int side = b / 208;
    int rem = b - side * 208;
    int rg = rem / 26, kg = rem - (rem / 26) * 26;
    const float* W = side ? Wd : Ws;
    int g = lane >> 2, tig = lane & 3;
    int r0 = rg * 16;
    int rows[2] = {r0 + g, r0 + g + 8};
    int cols[2] = {kg * 16 + 2 * tig, kg * 16 + 8 + 2 * tig};
    uint32_t w[4];
    #pragma unroll
    for (int cc = 0; cc < 2; cc++)
        #pragma unroll
        for (int rr = 0; rr < 2; rr++) {
            float2 v = *(const float2*)(W + (size_t)rows[rr] * 416 + cols[cc]);
            uint32_t hi, lo; bfsplit(v.x, v.y, hi, lo);
            w[cc * 2 + rr] = lo;
            (void)hi;
        }
    g_wpk[(size_t)b * 32 + lane] = make_uint4(w[0], w[1], w[2], w[3]);
}

// ============================================================
// Message MLP: mma.sync bf16 3-sweep, 512 threads / 16 warps, K-split pairs.
// Wlo fragments from global (L1/L2); smem = X only -> 2 CTAs/SM.
// ============================================================
__global__ void __launch_bounds__(512, 2) k_msgT(
    const float* __restrict__ mem, const float* __restrict__ raw,
    const float* __restrict__ tw,  const float* __restrict__ tb,
    const float* __restrict__ Ws,  const float* __restrict__ bs,
    const float* __restrict__ Wd,  const float* __restrict__ bd,
    const int* __restrict__ src, const int* __restrict__ dst,
    const int* __restrict__ tt,  const int* __restrict__ lu)
{
    extern __shared__ char smem[];
    uint32_t* xhi = (uint32_t*)(smem + M_XHI);
    uint32_t* xlo = (uint32_t*)(smem + M_XLO);
    float* stage  = (float*)(smem + M_STG);

    const int tid  = threadIdx.x;
    const int wid  = tid >> 5;
    const int lane = tid & 31;
    const int g    = lane >> 2;
    const int tig  = lane & 3;
    const int half = wid >> 3;
    const int ks   = half * 13;
    const int side = (blockIdx.x >= NB);
    const int bid  = side ? blockIdx.x - NB : blockIdx.x;
    const float* W    = side ? Wd : Ws;
    const float* bias = side ? bd : bs;
    const int r0 = (wid & 7) * 16;
    const size_t wbase = ((size_t)side * 208 + (size_t)(wid & 7) * 26) * 32 + lane;

    uint32_t whi[13][4];
    {
        const float* w0 = W + (size_t)(r0 + g) * 416 + ks * 16 + 2 * tig;
        const float* w8 = w0 + 8 * 416;
        #pragma unroll
        for (int kk = 0; kk < 13; kk++) {
            whi[kk][0] = bfhi(*(const float2*)(w0 + kk * 16));
            whi[kk][1] = bfhi(*(const float2*)(w8 + kk * 16));
            whi[kk][2] = bfhi(*(const float2*)(w0 + kk * 16 + 8));
            whi[kk][3] = bfhi(*(const float2*)(w8 + kk * 16 + 8));
        }
    }
    const float b0r = bias[r0 + g], b1r = bias[r0 + g + 8];
    const float twj = tw[lane], tbj = tb[lane];

    for (int e0 = bid * 64; e0 < EE; e0 += NB * 64) {
        // ---- gather + split X (cols 0..383) ----
        for (int idx = tid; idx < 64 * 96; idx += 512) {
            int ev = idx / 96, c4 = idx - (idx / 96) * 96;
            int e = e0 + ev;
            int vs = src[e], vd = dst[e];
            int a = side ? vd : vs, b = side ? vs : vd;
            const float4* p; int f4;
            if (c4 < 32)      { p = (const float4*)(mem + (size_t)a * DD); f4 = c4; }
            else if (c4 < 64) { p = (const float4*)(mem + (size_t)b * DD); f4 = c4 - 32; }
            else              { p = (const float4*)(raw + (size_t)e * RR); f4 = c4 - 64; }
            float4 v = p[f4];
            uint2 hi, lo; split4(v, hi, lo);
            int q = c4 & 3;
            int w = (c4 >> 2) * 8 + (q >> 1) + (q & 1) * 4;
            uint32_t* xh = xhi + ev * MXW + w;
            uint32_t* xl = xlo + ev * MXW + w;
            xh[0] = hi.x; xh[2] = hi.y;
            xl[0] = lo.x; xl[2] = lo.y;
        }
        // ---- time encoding (fp32-only Cody-Waite) ----
        #pragma unroll
        for (int z = 0; z < 4; z++) {
            int ev = wid + z * 16;
            int e = e0 + ev;
            int a = side ? dst[e] : src[e];
            float trel = __fsub_rn((float)tt[e], (float)lu[a]);
            float arg  = __fadd_rn(__fmul_rn(trel, twj), tbj);
            float c = cos_exact(arg);
            __nv_bfloat16 h = __float2bfloat16(c);
            __nv_bfloat16 l = __float2bfloat16(c - __bfloat162float(h));
            int k  = 384 + lane;
            int p  = k >> 1;
            int pi = p & 7, kk = p >> 3;
            int w  = kk * 8 + ((pi < 4) ? 2 * pi : 2 * (pi - 4) + 1);
            int byo = ev * MXROW + w * 4 + (k & 1) * 2;
            *(__nv_bfloat16*)((char*)smem + M_XHI + byo) = h;
            *(__nv_bfloat16*)((char*)smem + M_XLO + byo) = l;
        }
        __syncthreads();

        // ---- mma: 3 sweeps over this warp's 13 k-steps ----
        float acc[8][4];
        #pragma unroll
        for (int et = 0; et < 8; et++)
            acc[et][0] = acc[et][1] = acc[et][2] = acc[et][3] = 0.f;
        #pragma unroll
        for (int kk = 0; kk < 13; kk++) {
            int kg = ks + kk;
            uint4 wl = __ldg(&g_wpk[wbase + (size_t)kg * 32]);
            #pragma unroll
            for (int et = 0; et < 8; et++) {
                uint2 bh = *(const uint2*)(xhi + (et * 8 + g) * MXW + kg * 8 + 2 * tig);
                uint2 bl = *(const uint2*)(xlo + (et * 8 + g) * MXW + kg * 8 + 2 * tig);
                mma16816(acc[et], whi[kk][0], whi[kk][1], whi[kk][2], whi[kk][3], bh.x, bh.y);
                mma16816(acc[et], wl.x, wl.y, wl.z, wl.w, bh.x, bh.y);
                mma16816(acc[et], whi[kk][0], whi[kk][1], whi[kk][2], whi[kk][3], bl.x, bl.y);
            }
        }
        __syncthreads();

        // ---- combine K halves through stage ----
        if (half) {
            #pragma unroll
            for (int et = 0; et < 8; et++) {
                int evl = et * 8 + 2 * tig;
                stage[evl * 132 + r0 + g]           = acc[et][0];
                stage[(evl + 1) * 132 + r0 + g]     = acc[et][1];
                stage[evl * 132 + r0 + g + 8]       = acc[et][2];
                stage[(evl + 1) * 132 + r0 + g + 8] = acc[et][3];
            }
        }
        __syncthreads();
        if (!half) {
            #pragma unroll
            for (int et = 0; et < 8; et++) {
                int evl = et * 8 + 2 * tig;
                float* s0 = stage + evl * 132;
                float* s1 = stage + (evl + 1) * 132;
                s0[r0 + g]     = fmaxf(acc[et][0] + s0[r0 + g]     + b0r, 0.f);
                s1[r0 + g]     = fmaxf(acc[et][1] + s1[r0 + g]     + b0r, 0.f);
                s0[r0 + g + 8] = fmaxf(acc[et][2] + s0[r0 + g + 8] + b1r, 0.f);
                s1[r0 + g + 8] = fmaxf(acc[et][3] + s1[r0 + g + 8] + b1r, 0.f);
            }
        }
        __syncthreads();

        // ---- scatter float4 atomics ----
        #pragma unroll
        for (int it = 0; it < 4; it++) {
            int idx = tid + it * 512;
            int ev = idx >> 5, q = idx & 31;
            int e = e0 + ev;
            int key = side ? dst[e] : src[e];
            float4 v = *(const float4*)(stage + ev * 132 + q * 4);
            atomicAdd((float4*)&g_sums[(size_t)key * DD + q * 4], v);
        }
        if (tid < 64) {
            int e = e0 + tid;
            int key = side ? dst[e] : src[e];
            atomicAdd(&g_cnt[key], 1.0f);
            atomicMax(&g_tmax[key], tt[e]);
        }
        __syncthreads();
    }
}

// ============================================================
// gi = aggr @ W_ih^T + b_ih via mma.sync -> fp16 g_gih
// ============================================================
__global__ void __launch_bounds__(384, 1) k_gi2(
    const float* __restrict__ Wih, const float* __restrict__ bih)
{
    extern __shared__ char smem[];
    uint32_t* wlo = (uint32_t*)(smem + GI_WLO);
    uint32_t* xhi = (uint32_t*)(smem + GI_XHI);
    uint32_t* xlo = (uint32_t*)(smem + GI_XLO);
    float* stage  = (float*)(smem + GI_STG);

    const int tid = threadIdx.x;
    const int wid = tid >> 5;
    const int lane = tid & 31;
    const int g = lane >> 2, tig = lane & 3;

    for (int idx = tid; idx < GOUT * 32; idx += 384) {
        int r = idx >> 5, c4 = idx & 31;
        float4 v = ((const float4*)Wih)[idx];
        uint2 hi, lo; split4(v, hi, lo);
        *(uint2*)((char*)smem + GI_WLO + (size_t)r * (GWLW * 4) + c4 * 8) = lo;
        (void)hi;
    }
    uint32_t whi[2][8][4];
    float bv[2][2];
    #pragma unroll
    for (int rt = 0; rt < 2; rt++) {
        int r = wid * 32 + rt * 16 + g;
        const float* w0 = Wih + (size_t)r * 128 + 2 * tig;
        const float* w8 = w0 + 8 * 128;
        #pragma unroll
        for (int kk = 0; kk < 8; kk++) {
            whi[rt][kk][0] = bfhi(*(const float2*)(w0 + kk * 16));
            whi[rt][kk][1] = bfhi(*(const float2*)(w8 + kk * 16));
            whi[rt][kk][2] = bfhi(*(const float2*)(w0 + kk * 16 + 8));
            whi[rt][kk][3] = bfhi(*(const float2*)(w8 + kk * 16 + 8));
        }
        bv[rt][0] = bih[r]; bv[rt][1] = bih[r + 8];
    }
    __syncthreads();

    for (int n0 = blockIdx.x * 32; n0 < NN; n0 += gridDim.x * 32) {
        for (int idx = tid; idx < 32 * 32; idx += 384) {
            int n = idx >> 5, c4 = idx & 31;
            float4 v = ((const float4*)g_sums)[(size_t)(n0 + n) * 32 + c4];
            float inv = 1.0f / fmaxf(g_cnt[n0 + n], 1.0f);
            v.x *= inv; v.y *= inv; v.z *= inv; v.w *= inv;
            uint2 hi, lo; split4(v, hi, lo);
            int q = c4 & 3;
            int w = (c4 >> 2) * 8 + (q >> 1) + (q & 1) * 4;
            uint32_t* xh = xhi + n * GXW + w;
            uint32_t* xl = xlo + n * GXW + w;
            xh[0] = hi.x; xh[2] = hi.y;
            xl[0] = lo.x; xl[2] = lo.y;
        }
        __syncthreads();

        float acc[2][4][4];
        #pragma unroll
        for (int rt = 0; rt < 2; rt++)
            #pragma unroll
            for (int et = 0; et < 4; et++)
                acc[rt][et][0] = acc[rt][et][1] = acc[rt][et][2] = acc[rt][et][3] = 0.f;
        #pragma unroll
        for (int kk = 0; kk < 8; kk++) {
            uint2 bh[4], bl[4];
            #pragma unroll
            for (int et = 0; et < 4; et++) {
                bh[et] = *(const uint2*)(xhi + (et * 8 + g) * GXW + kk * 8 + 2 * tig);
                bl[et] = *(const uint2*)(xlo + (et * 8 + g) * GXW + kk * 8 + 2 * tig);
            }
            #pragma unroll
            for (int rt = 0; rt < 2; rt++) {
                int r = wid * 32 + rt * 16 + g;
                uint32_t a0 = wlo[r * GWLW + kk * 8 + tig];
                uint32_t a1 = wlo[(r + 8) * GWLW + kk * 8 + tig];
                uint32_t a2 = wlo[r * GWLW + kk * 8 + tig + 4];
                uint32_t a3 = wlo[(r + 8) * GWLW + kk * 8 + tig + 4];
                #pragma unroll
                for (int et = 0; et < 4; et++) {
                    mma16816(acc[rt][et], whi[rt][kk][0], whi[rt][kk][1], whi[rt][kk][2], whi[rt][kk][3], bh[et].x, bh[et].y);
                    mma16816(acc[rt][et], a0, a1, a2, a3, bh[et].x, bh[et].y);
                    mma16816(acc[rt][et], whi[rt][kk][0], whi[rt][kk][1], whi[rt][kk][2], whi[rt][kk][3], bl[et].x, bl[et].y);
                }
            }
        }
        #pragma unroll
        for (int rt = 0; rt < 2; rt++) {
            int r = wid * 32 + rt * 16 + g;
            #pragma unroll
            for (int et = 0; et < 4; et++) {
                int nl = et * 8 + 2 * tig;
                stage[nl * GSTG + r]           = acc[rt][et][0] + bv[rt][0];
                stage[(nl + 1) * GSTG + r]     = acc[rt][et][1] + bv[rt][0];
                stage[nl * GSTG + r + 8]       = acc[rt][et][2] + bv[rt][1];
                stage[(nl + 1) * GSTG + r + 8] = acc[rt][et][3] + bv[rt][1];
            }
        }
        __syncthreads();
        for (int idx = tid; idx < 32 * 96; idx += 384) {
            int n = idx / 96, c4 = idx - (idx / 96) * 96;
            float4 v = *(const float4*)(stage + n * GSTG + c4 * 4);
            __half2 h0 = __floats2half2_rn(v.x, v.y);
            __half2 h1 = __floats2half2_rn(v.z, v.w);
            uint2 u;
            u.x = *reinterpret_cast<uint32_t*>(&h0);
            u.y = *reinterpret_cast<uint32_t*>(&h1);
            g_gih[(size_t)(n0 + n) * 96 + c4] = u;
        }
        __syncthreads();
    }
}

// ============================================================
// gh = mem @ W_hh^T + b_hh via mma.sync + fused GRU combine
// ============================================================
__global__ void __launch_bounds__(384, 1) k_out2(
    const float* __restrict__ Whh, const float* __restrict__ bhh,
    const float* __restrict__ mem, float* __restrict__ out)
{
    extern __shared__ char smem[];
    uint32_t* wlo = (uint32_t*)(smem + GI_WLO);
    uint32_t* xhi = (uint32_t*)(smem + GI_XHI);
    uint32_t* xlo = (uint32_t*)(smem + GI_XLO);
    float* stage  = (float*)(smem + GI_STG);
    float* mraw   = (float*)(smem + OUT_MRAW);

    const int tid = threadIdx.x;
    const int wid = tid >> 5;
    const int lane = tid & 31;
    const int g = lane >> 2, tig = lane & 3;

    for (int idx = tid; idx < GOUT * 32; idx += 384) {
        int r = idx >> 5, c4 = idx & 31;
        float4 v = ((const float4*)Whh)[idx];
        uint2 hi, lo; split4(v, hi, lo);
        *(uint2*)((char*)smem + GI_WLO + (size_t)r * (GWLW * 4) + c4 * 8) = lo;
        (void)hi;
    }
    uint32_t whi[2][8][4];
    float bv[2][2];
    #pragma unroll
    for (int rt = 0; rt < 2; rt++) {
        int r = wid * 32 + rt * 16 + g;
        const float* w0 = Whh + (size_t)r * 128 + 2 * tig;
        const float* w8 = w0 + 8 * 128;
        #pragma unroll
        for (int kk = 0; kk < 8; kk++) {
            whi[rt][kk][0] = bfhi(*(const float2*)(w0 + kk * 16));
            whi[rt][kk][1] = bfhi(*(const float2*)(w8 + kk * 16));
            whi[rt][kk][2] = bfhi(*(const float2*)(w0 + kk * 16 + 8));
            whi[rt][kk][3] = bfhi(*(const float2*)(w8 + kk * 16 + 8));
        }
        bv[rt][0] = bhh[r]; bv[rt][1] = bhh[r + 8];
    }
    __syncthreads();

    for (int n0 = blockIdx.x * 32; n0 < NN; n0 += gridDim.x * 32) {
        for (int idx = tid; idx < 32 * 32; idx += 384) {
            int n = idx >> 5, c4 = idx & 31;
            float4 v = ((const float4*)mem)[(size_t)(n0 + n) * 32 + c4];
            *(float4*)(mraw + n * 132 + c4 * 4) = v;
            uint2 hi, lo; split4(v, hi, lo);
            int q = c4 & 3;
            int w = (c4 >> 2) * 8 + (q >> 1) + (q & 1) * 4;
            uint32_t* xh = xhi + n * GXW + w;
            uint32_t* xl = xlo + n * GXW + w;
            xh[0] = hi.x; xh[2] = hi.y;
            xl[0] = lo.x; xl[2] = lo.y;
        }
        __syncthreads();

        float acc[2][4][4];
        #pragma unroll
        for (int rt = 0; rt < 2; rt++)
            #pragma unroll
            for (int et = 0; et < 4; et++)
                acc[rt][et][0] = acc[rt][et][1] = acc[rt][et][2] = acc[rt][et][3] = 0.f;
        #pragma unroll
        for (int kk = 0; kk < 8; kk++) {
            uint2 bh[4], bl[4];
            #pragma unroll
            for (int et = 0; et < 4; et++) {
                bh[et] = *(const uint2*)(xhi + (et * 8 + g) * GXW + kk * 8 + 2 * tig);
                bl[et] = *(const uint2*)(xlo + (et * 8 + g) * GXW + kk * 8 + 2 * tig);
            }
            #pragma unroll
            for (int rt = 0; rt < 2; rt++) {
                int r = wid * 32 + rt * 16 + g;
                uint32_t a0 = wlo[r * GWLW + kk * 8 + tig];
                uint32_t a1 = wlo[(r + 8) * GWLW + kk * 8 + tig];
                uint32_t a2 = wlo[r * GWLW + kk * 8 + tig + 4];
                uint32_t a3 = wlo[(r + 8) * GWLW + kk * 8 + tig + 4];
                #pragma unroll
                for (int et = 0; et < 4; et++) {
                    mma16816(acc[rt][et], whi[rt][kk][0], whi[rt][kk][1], whi[rt][kk][2], whi[rt][kk][3], bh[et].x, bh[et].y);
                    mma16816(acc[rt][et], a0, a1, a2, a3, bh[et].x, bh[et].y);
                    mma16816(acc[rt][et], whi[rt][kk][0], whi[rt][kk][1], whi[rt][kk][2], whi[rt][kk][3], bl[et].x, bl[et].y);
                }
            }
        }
        #pragma unroll
        for (int rt = 0; rt < 2; rt++) {
            int r = wid * 32 + rt * 16 + g;
            #pragma unroll
            for (int et = 0; et < 4; et++) {
                int nl = et * 8 + 2 * tig;
                stage[nl * GSTG + r]           = acc[rt][et][0] + bv[rt][0];
                stage[(nl + 1) * GSTG + r]     = acc[rt][et][1] + bv[rt][0];
                stage[nl * GSTG + r + 8]       = acc[rt][et][2] + bv[rt][1];
                stage[(nl + 1) * GSTG + r + 8] = acc[rt][et][3] + bv[rt][1];
            }
        }
        __syncthreads();

        for (int idx = tid; idx < 32 * 32; idx += 384) {
            int n = idx >> 5, c4 = idx & 31;
            size_t gb = (size_t)(n0 + n) * 96 + c4;
            uint2 uir = g_gih[gb];
            uint2 uiz = g_gih[gb + 32];
            uint2 uin = g_gih[gb + 64];
            float2 ir01 = __half22float2(*reinterpret_cast<__half2*>(&uir.x));
            float2 ir23 = __half22float2(*reinterpret_cast<__half2*>(&uir.y));
            float2 iz01 = __half22float2(*reinterpret_cast<__half2*>(&uiz.x));
            float2 iz23 = __half22float2(*reinterpret_cast<__half2*>(&uiz.y));
            float2 in01 = __half22float2(*reinterpret_cast<__half2*>(&uin.x));
            float2 in23 = __half22float2(*reinterpret_cast<__half2*>(&uin.y));
            float4 hr = *(const float4*)(stage + n * GSTG + c4 * 4);
            float4 hz = *(const float4*)(stage + n * GSTG + 128 + c4 * 4);
            float4 hn = *(const float4*)(stage + n * GSTG + 256 + c4 * 4);
            float4 m = *(const float4*)(mraw + n * 132 + c4 * 4);
            float4 o;
            { float rg = 1.f/(1.f+expf(-(ir01.x+hr.x))), zg = 1.f/(1.f+expf(-(iz01.x+hz.x)));
              o.x = (1.f-zg)*tanhf(in01.x+rg*hn.x) + zg*m.x; }
            { float rg = 1.f/(1.f+expf(-(ir01.y+hr.y))), zg = 1.f/(1.f+expf(-(iz01.y+hz.y)));
              o.y = (1.f-zg)*tanhf(in01.y+rg*hn.y) + zg*m.y; }
            { float rg = 1.f/(1.f+expf(-(ir23.x+hr.z))), zg = 1.f/(1.f+expf(-(iz23.x+hz.z)));
              o.z = (1.f-zg)*tanhf(in23.x+rg*hn.z) + zg*m.z; }
            { float rg = 1.f/(1.f+expf(-(ir23.y+hr.w))), zg = 1.f/(1.f+expf(-(iz23.y+hz.w)));
              o.w = (1.f-zg)*tanhf(in23.y+rg*hn.w) + zg*m.w; }
            *(float4*)(out + (size_t)(n0 + n) * DD + c4 * 4) = o;
        }
        __syncthreads();
    }
}

// ============================================================
__global__ void k_lu(float* __restrict__ out) {
    int i = blockIdx.x * blockDim.x + threadIdx.x;
    if (i < NN)
        out[(size_t)NN * DD + i] = (g_cnt[i] > 0.f) ? (float)g_tmax[i] : 0.f;
}

// ============================================================
extern "C" void kernel_launch(void* const* d_in, const int* in_sizes, int n_in,
                              void* d_out, int out_size)
{
    const float* mem = (const float*)d_in[0];
    const float* raw = (const float*)d_in[1];
    const float* tw  = (const float*)d_in[2];
    const float* tb  = (const float*)d_in[3];
    const float* Ws  = (const float*)d_in[4];
    const float* bs  = (const float*)d_in[5];
    const float* Wd  = (const float*)d_in[6];
    const float* bd  = (const float*)d_in[7];
    const float* Wih = (const float*)d_in[8];
    const float* Whh = (const float*)d_in[9];
    const float* bih = (const float*)d_in[10];
    const float* bhh = (const float*)d_in[11];
    const int* src = (const int*)d_in[12];
    const int* dst = (const int*)d_in[13];
    const int* tt  = (const int*)d_in[14];
    const int* lu  = (const int*)d_in[15];
    float* out = (float*)d_out;

    cudaFuncSetAttribute(k_msgT, cudaFuncAttributeMaxDynamicSharedMemorySize, SMEM_MSG);
    cudaFuncSetAttribute(k_gi2,  cudaFuncAttributeMaxDynamicSharedMemorySize, GI_SMEM);
    cudaFuncSetAttribute(k_out2, cudaFuncAttributeMaxDynamicSharedMemorySize, OUT_SMEM);

    k_init<<<2048, 256>>>();
    k_pack<<<416, 32>>>(Ws, Wd);
    k_msgT<<<2 * NB, 512, SMEM_MSG>>>(mem, raw, tw, tb, Ws, bs, Wd, bd, src, dst, tt, lu);
    k_gi2 <<<NB, 384, GI_SMEM>>>(Wih, bih);
    k_out2<<<NB, 384, OUT_SMEM>>>(Whh, bhh, mem, out);
    if (out_size >= NN * DD + NN)
        k_lu<<<(NN + 255) / 256, 256>>>(out);
}

// round 11
// speedup vs baseline: 2.3027x; 1.0529x over previous
#include <cuda_runtime.h>
#include <cuda_bf16.h>
#include <cuda_fp16.h>
#include <math.h>
#include <stdint.h>

#define NN 131072
#define EE 262144
#define DD 128
#define RR 128
#define NB 148
#define GOUT 384

#define TWO_PI_C1 6.2831854820251465f
#define TWO_PI_C2 (-1.7484556e-7f)
#define INV_2PI   0.15915494309189535f

// ---- k_msgT smem layout: X only ----
#define MXW 212                        // X row stride words (mod32=20 -> conflict-free)
#define MXROW (MXW * 4)
#define M_XHI 0                        // 64*848 = 54272
#define M_XLO 54272
#define SMEM_MSG (2 * 54272)           // 108544 -> 2 CTAs/SM
#define M_STG M_XHI

// ---- GRU smem layout ----
#define GWLW 68
#define GXW 72
#define GSTG 388
#define GI_WLO 0
#define GI_XHI 104448
#define GI_XLO (GI_XHI + 9216)
#define GI_STG (GI_XLO + 9216)
#define GI_SMEM (GI_STG + 49664)
#define OUT_MRAW GI_SMEM
#define OUT_SMEM (OUT_MRAW + 16896)

// -------- device scratch --------
__device__ float g_sums[(size_t)NN * DD];
__device__ float g_cnt[NN];
__device__ int   g_tmax[NN];
__device__ uint2 g_gih[(size_t)NN * 96];            // gi in fp16
__device__ uint4 g_wpk[2 * 8 * 26 * 32];            // Wlo mma fragments
__device__ uint32_t g_memhi[(size_t)NN * 64];       // memory bf16-hi, permuted pairs
__device__ uint32_t g_memlo[(size_t)NN * 64];
__device__ uint32_t g_rawhi[(size_t)EE * 64];       // raw bf16-hi, permuted pairs
__device__ uint32_t g_rawlo[(size_t)EE * 64];

// ================= helpers =================
__device__ __forceinline__ void mma16816(float* c,
                                         uint32_t a0, uint32_t a1, uint32_t a2, uint32_t a3,
                                         uint32_t b0, uint32_t b1) {
    asm volatile("mma.sync.aligned.m16n8k16.row.col.f32.bf16.bf16.f32 "
        "{%0,%1,%2,%3}, {%4,%5,%6,%7}, {%8,%9}, {%0,%1,%2,%3};"
        : "+f"(c[0]), "+f"(c[1]), "+f"(c[2]), "+f"(c[3])
        : "r"(a0), "r"(a1), "r"(a2), "r"(a3), "r"(b0), "r"(b1));
}
__device__ __forceinline__ uint32_t bfhi(float2 p) {
    __nv_bfloat162 h = __floats2bfloat162_rn(p.x, p.y);
    return *reinterpret_cast<uint32_t*>(&h);
}
__device__ __forceinline__ void bfsplit(float x, float y, uint32_t& hi, uint32_t& lo) {
    __nv_bfloat162 h = __floats2bfloat162_rn(x, y);
    float rx = x - __bfloat162float(h.x);
    float ry = y - __bfloat162float(h.y);
    __nv_bfloat162 l = __floats2bfloat162_rn(rx, ry);
    hi = *reinterpret_cast<uint32_t*>(&h);
    lo = *reinterpret_cast<uint32_t*>(&l);
}
__device__ __forceinline__ void split4(float4 v, uint2& hi, uint2& lo) {
    bfsplit(v.x, v.y, hi.x, lo.x);
    bfsplit(v.z, v.w, hi.y, lo.y);
}
__device__ __forceinline__ float cos_exact(float arg) {
    float k = rintf(__fmul_rn(arg, INV_2PI));
    float r = fmaf(-k, TWO_PI_C1, arg);
    r = fmaf(-k, TWO_PI_C2, r);
    return cosf(r);
}
// permuted slot within an 8-word k-step group (matches mma B-fragment layout)
__device__ __forceinline__ int permslot(int p) {
    int kk = p >> 3, pi = p & 7;
    return kk * 8 + ((pi < 4) ? 2 * pi : 2 * (pi - 4) + 1);
}

// ============================================================
__global__ void k_init() {
    size_t i = (size_t)blockIdx.x * blockDim.x + threadIdx.x;
    size_t stride = (size_t)gridDim.x * blockDim.x;
    float4* s4 = (float4*)g_sums;
    for (size_t idx = i; idx < (size_t)NN * DD / 4; idx += stride)
        s4[idx] = make_float4(0.f, 0.f, 0.f, 0.f);
    for (size_t idx = i; idx < NN; idx += stride) { g_cnt[idx] = 0.f; g_tmax[idx] = 0; }
}

// ============================================================
// Prepack memory + raw into bf16 hi/lo permuted word arrays.
// ============================================================
__global__ void k_packmem(const float* __restrict__ mem) {
    size_t i = (size_t)blockIdx.x * blockDim.x + threadIdx.x;
    size_t stride = (size_t)gridDim.x * blockDim.x;
    for (size_t idx = i; idx < (size_t)NN * 64; idx += stride) {
        size_t n = idx >> 6; int p = (int)(idx & 63);
        float2 v = *(const float2*)(mem + n * 128 + 2 * p);
        uint32_t hi, lo; bfsplit(v.x, v.y, hi, lo);
        size_t d = n * 64 + permslot(p);
        g_memhi[d] = hi; g_memlo[d] = lo;
    }
}
__global__ void k_packraw(const float* __restrict__ raw) {
    size_t i = (size_t)blockIdx.x * blockDim.x + threadIdx.x;
    size_t stride = (size_t)gridDim.x * blockDim.x;
    for (size_t idx = i; idx < (size_t)EE * 64; idx += stride) {
        size_t e = idx >> 6; int p = (int)(idx & 63);
        float2 v = *(const float2*)(raw + e * 128 + 2 * p);
        uint32_t hi, lo; bfsplit(v.x, v.y, hi, lo);
        size_t d = e * 64 + permslot(p);
        g_rawhi[d] = hi; g_rawlo[d] = lo;
    }
}

// ============================================================
// Prepack Wlo mma A-fragments (unchanged from round 10)
// ============================================================
__global__ void k_pack(const float* __restrict__ Ws, const float* __restrict__ Wd) {
    int lane = threadIdx.x;
    int b = blockIdx.x;
    int side = b / 208;
    int rem = b - side * 208;
    int rg = rem / 26, kg = rem - (rem / 26) * 26;
    const float* W = side ? Wd : Ws;
    int g = lane >> 2, tig = lane & 3;
    int r0 = rg * 16;
    int rows[2] = {r0 + g, r0 + g + 8};
    int cols[2] = {kg * 16 + 2 * tig, kg * 16 + 8 + 2 * tig};
    uint32_t w[4];
    #pragma unroll
    for (int cc = 0; cc < 2; cc++)
        #pragma unroll
        for (int rr = 0; rr < 2; rr++) {
            float2 v = *(const float2*)(W + (size_t)rows[rr] * 416 + cols[cc]);
            uint32_t hi, lo; bfsplit(v.x, v.y, hi, lo);
            w[cc * 2 + rr] = lo;
            (void)hi;
        }
    g_wpk[(size_t)b * 32 + lane] = make_uint4(w[0], w[1], w[2], w[3]);
}

// ============================================================
// Message MLP: mma.sync bf16 3-sweep; gather is pure LDG.128->STS.128.
// ============================================================
__global__ void __launch_bounds__(512, 2) k_msgT(
    const float* __restrict__ tw,  const float* __restrict__ tb,
    const float* __restrict__ Ws,  const float* __restrict__ bs,
    const float* __restrict__ Wd,  const float* __restrict__ bd,
    const int* __restrict__ src, const int* __restrict__ dst,
    const int* __restrict__ tt,  const int* __restrict__ lu)
{
    extern __shared__ char smem[];
    uint32_t* xhi = (uint32_t*)(smem + M_XHI);
    uint32_t* xlo = (uint32_t*)(smem + M_XLO);
    float* stage  = (float*)(smem + M_STG);

    const int tid  = threadIdx.x;
    const int wid  = tid >> 5;
    const int lane = tid & 31;
    const int g    = lane >> 2;
    const int tig  = lane & 3;
    const int half = wid >> 3;
    const int ks   = half * 13;
    const int side = (blockIdx.x >= NB);
    const int bid  = side ? blockIdx.x - NB : blockIdx.x;
    const float* W    = side ? Wd : Ws;
    const float* bias = side ? bd : bs;
    const int r0 = (wid & 7) * 16;
    const size_t wbase = ((size_t)side * 208 + (size_t)(wid & 7) * 26) * 32 + lane;

    uint32_t whi[13][4];
    {
        const float* w0 = W + (size_t)(r0 + g) * 416 + ks * 16 + 2 * tig;
        const float* w8 = w0 + 8 * 416;
        #pragma unroll
        for (int kk = 0; kk < 13; kk++) {
            whi[kk][0] = bfhi(*(const float2*)(w0 + kk * 16));
            whi[kk][1] = bfhi(*(const float2*)(w8 + kk * 16));
            whi[kk][2] = bfhi(*(const float2*)(w0 + kk * 16 + 8));
            whi[kk][3] = bfhi(*(const float2*)(w8 + kk * 16 + 8));
        }
    }
    const float b0r = bias[r0 + g], b1r = bias[r0 + g + 8];
    const float twj = tw[lane], tbj = tb[lane];

    for (int e0 = bid * 64; e0 < EE; e0 += NB * 64) {
        // ---- gather (prepacked, zero math): 64 ev x 48 uint4 per array ----
        #pragma unroll
        for (int it = 0; it < 6; it++) {
            int idx = tid + it * 512;
            int ev = idx / 48, c16 = idx - (idx / 48) * 48;
            int e = e0 + ev;
            int vs = src[e], vd = dst[e];
            int a = side ? vd : vs, b = side ? vs : vd;
            size_t base;
            const uint32_t *phi, *plo;
            if (c16 < 16)      { base = (size_t)a * 64 + c16 * 4;        phi = g_memhi; plo = g_memlo; }
            else if (c16 < 32) { base = (size_t)b * 64 + (c16 - 16) * 4; phi = g_memhi; plo = g_memlo; }
            else               { base = (size_t)e * 64 + (c16 - 32) * 4; phi = g_rawhi; plo = g_rawlo; }
            uint4 h4 = *(const uint4*)(phi + base);
            uint4 l4 = *(const uint4*)(plo + base);
            *(uint4*)(xhi + ev * MXW + c16 * 4) = h4;
            *(uint4*)(xlo + ev * MXW + c16 * 4) = l4;
        }
        // ---- time encoding (fp32-only Cody-Waite) ----
        #pragma unroll
        for (int z = 0; z < 4; z++) {
            int ev = wid + z * 16;
            int e = e0 + ev;
            int a = side ? dst[e] : src[e];
            float trel = __fsub_rn((float)tt[e], (float)lu[a]);
            float arg  = __fadd_rn(__fmul_rn(trel, twj), tbj);
            float c = cos_exact(arg);
            __nv_bfloat16 h = __float2bfloat16(c);
            __nv_bfloat16 l = __float2bfloat16(c - __bfloat162float(h));
            int k  = 384 + lane;
            int p  = k >> 1;
            int w  = permslot(p & 63) + ((p >> 6) << 6);   // p in [192,208): group 24,25
            // simpler: global word = (p>>3)*8 + perm within group
            int pi = p & 7, kk = p >> 3;
            w = kk * 8 + ((pi < 4) ? 2 * pi : 2 * (pi - 4) + 1);
            int byo = ev * MXROW + w * 4 + (k & 1) * 2;
            *(__nv_bfloat16*)((char*)smem + M_XHI + byo) = h;
            *(__nv_bfloat16*)((char*)smem + M_XLO + byo) = l;
        }
        __syncthreads();

        // ---- mma: 3 sweeps over this warp's 13 k-steps ----
        float acc[8][4];
        #pragma unroll
        for (int et = 0; et < 8; et++)
            acc[et][0] = acc[et][1] = acc[et][2] = acc[et][3] = 0.f;
        #pragma unroll
        for (int kk = 0; kk < 13; kk++) {
            int kg = ks + kk;
            uint4 wl = __ldg(&g_wpk[wbase + (size_t)kg * 32]);
            #pragma unroll
            for (int et = 0; et < 8; et++) {
                uint2 bh = *(const uint2*)(xhi + (et * 8 + g) * MXW + kg * 8 + 2 * tig);
                uint2 bl = *(const uint2*)(xlo + (et * 8 + g) * MXW + kg * 8 + 2 * tig);
                mma16816(acc[et], whi[kk][0], whi[kk][1], whi[kk][2], whi[kk][3], bh.x, bh.y);
                mma16816(acc[et], wl.x, wl.y, wl.z, wl.w, bh.x, bh.y);
                mma16816(acc[et], whi[kk][0], whi[kk][1], whi[kk][2], whi[kk][3], bl.x, bl.y);
            }
        }
        __syncthreads();

        // ---- combine K halves through stage ----
        if (half) {
            #pragma unroll
            for (int et = 0; et < 8; et++) {
                int evl = et * 8 + 2 * tig;
                stage[evl * 132 + r0 + g]           = acc[et][0];
                stage[(evl + 1) * 132 + r0 + g]     = acc[et][1];
                stage[evl * 132 + r0 + g + 8]       = acc[et][2];
                stage[(evl + 1) * 132 + r0 + g + 8] = acc[et][3];
            }
        }
        __syncthreads();
        if (!half) {
            #pragma unroll
            for (int et = 0; et < 8; et++) {
                int evl = et * 8 + 2 * tig;
                float* s0 = stage + evl * 132;
                float* s1 = stage + (evl + 1) * 132;
                s0[r0 + g]     = fmaxf(acc[et][0] + s0[r0 + g]     + b0r, 0.f);
                s1[r0 + g]     = fmaxf(acc[et][1] + s1[r0 + g]     + b0r, 0.f);
                s0[r0 + g + 8] = fmaxf(acc[et][2] + s0[r0 + g + 8] + b1r, 0.f);
                s1[r0 + g + 8] = fmaxf(acc[et][3] + s1[r0 + g + 8] + b1r, 0.f);
            }
        }
        __syncthreads();

        // ---- scatter float4 atomics ----
        #pragma unroll
        for (int it = 0; it < 4; it++) {
            int idx = tid + it * 512;
            int ev = idx >> 5, q = idx & 31;
            int e = e0 + ev;
            int key = side ? dst[e] : src[e];
            float4 v = *(const float4*)(stage + ev * 132 + q * 4);
            atomicAdd((float4*)&g_sums[(size_t)key * DD + q * 4], v);
        }
        if (tid < 64) {
            int e = e0 + tid;
            int key = side ? dst[e] : src[e];
            atomicAdd(&g_cnt[key], 1.0f);
            atomicMax(&g_tmax[key], tt[e]);
        }
        __syncthreads();
    }
}

// ============================================================
// gi = aggr @ W_ih^T + b_ih via mma.sync -> fp16 g_gih (round-10 proven)
// ============================================================
__global__ void __launch_bounds__(384, 1) k_gi2(
    const float* __restrict__ Wih, const float* __restrict__ bih)
{
    extern __shared__ char smem[];
    uint32_t* wlo = (uint32_t*)(smem + GI_WLO);
    uint32_t* xhi = (uint32_t*)(smem + GI_XHI);
    uint32_t* xlo = (uint32_t*)(smem + GI_XLO);
    float* stage  = (float*)(smem + GI_STG);

    const int tid = threadIdx.x;
    const int wid = tid >> 5;
    const int lane = tid & 31;
    const int g = lane >> 2, tig = lane & 3;

    for (int idx = tid; idx < GOUT * 32; idx += 384) {
        int r = idx >> 5, c4 = idx & 31;
        float4 v = ((const float4*)Wih)[idx];
        uint2 hi, lo; split4(v, hi, lo);
        *(uint2*)((char*)smem + GI_WLO + (size_t)r * (GWLW * 4) + c4 * 8) = lo;
        (void)hi;
    }
    uint32_t whi[2][8][4];
    float bv[2][2];
    #pragma unroll
    for (int rt = 0; rt < 2; rt++) {
        int r = wid * 32 + rt * 16 + g;
        const float* w0 = Wih + (size_t)r * 128 + 2 * tig;
        const float* w8 = w0 + 8 * 128;
        #pragma unroll
        for (int kk = 0; kk < 8; kk++) {
            whi[rt][kk][0] = bfhi(*(const float2*)(w0 + kk * 16));
            whi[rt][kk][1] = bfhi(*(const float2*)(w8 + kk * 16));
            whi[rt][kk][2] = bfhi(*(const float2*)(w0 + kk * 16 + 8));
            whi[rt][kk][3] = bfhi(*(const float2*)(w8 + kk * 16 + 8));
        }
        bv[rt][0] = bih[r]; bv[rt][1] = bih[r + 8];
    }
    __syncthreads();

    for (int n0 = blockIdx.x * 32; n0 < NN; n0 += gridDim.x * 32) {
        for (int idx = tid; idx < 32 * 32; idx += 384) {
            int n = idx >> 5, c4 = idx & 31;
            float4 v = ((const float4*)g_sums)[(size_t)(n0 + n) * 32 + c4];
            float inv = 1.0f / fmaxf(g_cnt[n0 + n], 1.0f);
            v.x *= inv; v.y *= inv; v.z *= inv; v.w *= inv;
            uint2 hi, lo; split4(v, hi, lo);
            int q = c4 & 3;
            int w = (c4 >> 2) * 8 + (q >> 1) + (q & 1) * 4;
            uint32_t* xh = xhi + n * GXW + w;
            uint32_t* xl = xlo + n * GXW + w;
            xh[0] = hi.x; xh[2] = hi.y;
            xl[0] = lo.x; xl[2] = lo.y;
        }
        __syncthreads();

        float acc[2][4][4];
        #pragma unroll
        for (int rt = 0; rt < 2; rt++)
            #pragma unroll
            for (int et = 0; et < 4; et++)
                acc[rt][et][0] = acc[rt][et][1] = acc[rt][et][2] = acc[rt][et][3] = 0.f;
        #pragma unroll
        for (int kk = 0; kk < 8; kk++) {
            uint2 bh[4], bl[4];
            #pragma unroll
            for (int et = 0; et < 4; et++) {
                bh[et] = *(const uint2*)(xhi + (et * 8 + g) * GXW + kk * 8 + 2 * tig);
                bl[et] = *(const uint2*)(xlo + (et * 8 + g) * GXW + kk * 8 + 2 * tig);
            }
            #pragma unroll
            for (int rt = 0; rt < 2; rt++) {
                int r = wid * 32 + rt * 16 + g;
                uint32_t a0 = wlo[r * GWLW + kk * 8 + tig];
                uint32_t a1 = wlo[(r + 8) * GWLW + kk * 8 + tig];
                uint32_t a2 = wlo[r * GWLW + kk * 8 + tig + 4];
                uint32_t a3 = wlo[(r + 8) * GWLW + kk * 8 + tig + 4];
                #pragma unroll
                for (int et = 0; et < 4; et++) {
                    mma16816(acc[rt][et], whi[rt][kk][0], whi[rt][kk][1], whi[rt][kk][2], whi[rt][kk][3], bh[et].x, bh[et].y);
                    mma16816(acc[rt][et], a0, a1, a2, a3, bh[et].x, bh[et].y);
                    mma16816(acc[rt][et], whi[rt][kk][0], whi[rt][kk][1], whi[rt][kk][2], whi[rt][kk][3], bl[et].x, bl[et].y);
                }
            }
        }
        #pragma unroll
        for (int rt = 0; rt < 2; rt++) {
            int r = wid * 32 + rt * 16 + g;
            #pragma unroll
            for (int et = 0; et < 4; et++) {
                int nl = et * 8 + 2 * tig;
                stage[nl * GSTG + r]           = acc[rt][et][0] + bv[rt][0];
                stage[(nl + 1) * GSTG + r]     = acc[rt][et][1] + bv[rt][0];
                stage[nl * GSTG + r + 8]       = acc[rt][et][2] + bv[rt][1];
                stage[(nl + 1) * GSTG + r + 8] = acc[rt][et][3] + bv[rt][1];
            }
        }
        __syncthreads();
        for (int idx = tid; idx < 32 * 96; idx += 384) {
            int n = idx / 96, c4 = idx - (idx / 96) * 96;
            float4 v = *(const float4*)(stage + n * GSTG + c4 * 4);
            __half2 h0 = __floats2half2_rn(v.x, v.y);
            __half2 h1 = __floats2half2_rn(v.z, v.w);
            uint2 u;
            u.x = *reinterpret_cast<uint32_t*>(&h0);
            u.y = *reinterpret_cast<uint32_t*>(&h1);
            g_gih[(size_t)(n0 + n) * 96 + c4] = u;
        }
        __syncthreads();
    }
}

// ============================================================
// gh = mem @ W_hh^T + b_hh via mma.sync + fused GRU combine (round-10 proven)
// ============================================================
__global__ void __launch_bounds__(384, 1) k_out2(
    const float* __restrict__ Whh, const float* __restrict__ bhh,
    const float* __restrict__ mem, float* __restrict__ out)
{
    extern __shared__ char smem[];
    uint32_t* wlo = (uint32_t*)(smem + GI_WLO);
    uint32_t* xhi = (uint32_t*)(smem + GI_XHI);
    uint32_t* xlo = (uint32_t*)(smem + GI_XLO);
    float* stage  = (float*)(smem + GI_STG);
    float* mraw   = (float*)(smem + OUT_MRAW);

    const int tid = threadIdx.x;
    const int wid = tid >> 5;
    const int lane = tid & 31;
    const int g = lane >> 2, tig = lane & 3;

    for (int idx = tid; idx < GOUT * 32; idx += 384) {
        int r = idx >> 5, c4 = idx & 31;
        float4 v = ((const float4*)Whh)[idx];
        uint2 hi, lo; split4(v, hi, lo);
        *(uint2*)((char*)smem + GI_WLO + (size_t)r * (GWLW * 4) + c4 * 8) = lo;
        (void)hi;
    }
    uint32_t whi[2][8][4];
    float bv[2][2];
    #pragma unroll
    for (int rt = 0; rt < 2; rt++) {
        int r = wid * 32 + rt * 16 + g;
        const float* w0 = Whh + (size_t)r * 128 + 2 * tig;
        const float* w8 = w0 + 8 * 128;
        #pragma unroll
        for (int kk = 0; kk < 8; kk++) {
            whi[rt][kk][0] = bfhi(*(const float2*)(w0 + kk * 16));
            whi[rt][kk][1] = bfhi(*(const float2*)(w8 + kk * 16));
            whi[rt][kk][2] = bfhi(*(const float2*)(w0 + kk * 16 + 8));
            whi[rt][kk][3] = bfhi(*(const float2*)(w8 + kk * 16 + 8));
        }
        bv[rt][0] = bhh[r]; bv[rt][1] = bhh[r + 8];
    }
    __syncthreads();

    for (int n0 = blockIdx.x * 32; n0 < NN; n0 += gridDim.x * 32) {
        for (int idx = tid; idx < 32 * 32; idx += 384) {
            int n = idx >> 5, c4 = idx & 31;
            float4 v = ((const float4*)mem)[(size_t)(n0 + n) * 32 + c4];
            *(float4*)(mraw + n * 132 + c4 * 4) = v;
            uint2 hi, lo; split4(v, hi, lo);
            int q = c4 & 3;
            int w = (c4 >> 2) * 8 + (q >> 1) + (q & 1) * 4;
            uint32_t* xh = xhi + n * GXW + w;
            uint32_t* xl = xlo + n * GXW + w;
            xh[0] = hi.x; xh[2] = hi.y;
            xl[0] = lo.x; xl[2] = lo.y;
        }
        __syncthreads();

        float acc[2][4][4];
        #pragma unroll
        for (int rt = 0; rt < 2; rt++)
            #pragma unroll
            for (int et = 0; et < 4; et++)
                acc[rt][et][0] = acc[rt][et][1] = acc[rt][et][2] = acc[rt][et][3] = 0.f;
        #pragma unroll
        for (int kk = 0; kk < 8; kk++) {
            uint2 bh[4], bl[4];
            #pragma unroll
            for (int et = 0; et < 4; et++) {
                bh[et] = *(const uint2*)(xhi + (et * 8 + g) * GXW + kk * 8 + 2 * tig);
                bl[et] = *(const uint2*)(xlo + (et * 8 + g) * GXW + kk * 8 + 2 * tig);
            }
            #pragma unroll
            for (int rt = 0; rt < 2; rt++) {
                int r = wid * 32 + rt * 16 + g;
                uint32_t a0 = wlo[r * GWLW + kk * 8 + tig];
                uint32_t a1 = wlo[(r + 8) * GWLW + kk * 8 + tig];
                uint32_t a2 = wlo[r * GWLW + kk * 8 + tig + 4];
                uint32_t a3 = wlo[(r + 8) * GWLW + kk * 8 + tig + 4];
                #pragma unroll
                for (int et = 0; et < 4; et++) {
                    mma16816(acc[rt][et], whi[rt][kk][0], whi[rt][kk][1], whi[rt][kk][2], whi[rt][kk][3], bh[et].x, bh[et].y);
                    mma16816(acc[rt][et], a0, a1, a2, a3, bh[et].x, bh[et].y);
                    mma16816(acc[rt][et], whi[rt][kk][0], whi[rt][kk][1], whi[rt][kk][2], whi[rt][kk][3], bl[et].x, bl[et].y);
                }
            }
        }
        #pragma unroll
        for (int rt = 0; rt < 2; rt++) {
            int r = wid * 32 + rt * 16 + g;
            #pragma unroll
            for (int et = 0; et < 4; et++) {
                int nl = et * 8 + 2 * tig;
                stage[nl * GSTG + r]           = acc[rt][et][0] + bv[rt][0];
                stage[(nl + 1) * GSTG + r]     = acc[rt][et][1] + bv[rt][0];
                stage[nl * GSTG + r + 8]       = acc[rt][et][2] + bv[rt][1];
                stage[(nl + 1) * GSTG + r + 8] = acc[rt][et][3] + bv[rt][1];
            }
        }
        __syncthreads();

        for (int idx = tid; idx < 32 * 32; idx += 384) {
            int n = idx >> 5, c4 = idx & 31;
            size_t gb = (size_t)(n0 + n) * 96 + c4;
            uint2 uir = g_gih[gb];
            uint2 uiz = g_gih[gb + 32];
            uint2 uin = g_gih[gb + 64];
            float2 ir01 = __half22float2(*reinterpret_cast<__half2*>(&uir.x));
            float2 ir23 = __half22float2(*reinterpret_cast<__half2*>(&uir.y));
            float2 iz01 = __half22float2(*reinterpret_cast<__half2*>(&uiz.x));
            float2 iz23 = __half22float2(*reinterpret_cast<__half2*>(&uiz.y));
            float2 in01 = __half22float2(*reinterpret_cast<__half2*>(&uin.x));
            float2 in23 = __half22float2(*reinterpret_cast<__half2*>(&uin.y));
            float4 hr = *(const float4*)(stage + n * GSTG + c4 * 4);
            float4 hz = *(const float4*)(stage + n * GSTG + 128 + c4 * 4);
            float4 hn = *(const float4*)(stage + n * GSTG + 256 + c4 * 4);
            float4 m = *(const float4*)(mraw + n * 132 + c4 * 4);
            float4 o;
            { float rg = 1.f/(1.f+expf(-(ir01.x+hr.x))), zg = 1.f/(1.f+expf(-(iz01.x+hz.x)));
              o.x = (1.f-zg)*tanhf(in01.x+rg*hn.x) + zg*m.x; }
            { float rg = 1.f/(1.f+expf(-(ir01.y+hr.y))), zg = 1.f/(1.f+expf(-(iz01.y+hz.y)));
              o.y = (1.f-zg)*tanhf(in01.y+rg*hn.y) + zg*m.y; }
            { float rg = 1.f/(1.f+expf(-(ir23.x+hr.z))), zg = 1.f/(1.f+expf(-(iz23.x+hz.z)));
              o.z = (1.f-zg)*tanhf(in23.x+rg*hn.z) + zg*m.z; }
            { float rg = 1.f/(1.f+expf(-(ir23.y+hr.w))), zg = 1.f/(1.f+expf(-(iz23.y+hz.w)));
              o.w = (1.f-zg)*tanhf(in23.y+rg*hn.w) + zg*m.w; }
            *(float4*)(out + (size_t)(n0 + n) * DD + c4 * 4) = o;
        }
        __syncthreads();
    }
}

// ============================================================
__global__ void k_lu(float* __restrict__ out) {
    int i = blockIdx.x * blockDim.x + threadIdx.x;
    if (i < NN)
        out[(size_t)NN * DD + i] = (g_cnt[i] > 0.f) ? (float)g_tmax[i] : 0.f;
}

// ============================================================
extern "C" void kernel_launch(void* const* d_in, const int* in_sizes, int n_in,
                              void* d_out, int out_size)
{
    const float* mem = (const float*)d_in[0];
    const float* raw = (const float*)d_in[1];
    const float* tw  = (const float*)d_in[2];
    const float* tb  = (const float*)d_in[3];
    const float* Ws  = (const float*)d_in[4];
    const float* bs  = (const float*)d_in[5];
    const float* Wd  = (const float*)d_in[6];
    const float* bd  = (const float*)d_in[7];
    const float* Wih = (const float*)d_in[8];
    const float* Whh = (const float*)d_in[9];
    const float* bih = (const float*)d_in[10];
    const float* bhh = (const float*)d_in[11];
    const int* src = (const int*)d_in[12];
    const int* dst = (const int*)d_in[13];
    const int* tt  = (const int*)d_in[14];
    const int* lu  = (const int*)d_in[15];
    float* out = (float*)d_out;

    cudaFuncSetAttribute(k_msgT, cudaFuncAttributeMaxDynamicSharedMemorySize, SMEM_MSG);
    cudaFuncSetAttribute(k_gi2,  cudaFuncAttributeMaxDynamicSharedMemorySize, GI_SMEM);
    cudaFuncSetAttribute(k_out2, cudaFuncAttributeMaxDynamicSharedMemorySize, OUT_SMEM);

    k_init<<<2048, 256>>>();
    k_pack<<<416, 32>>>(Ws, Wd);
    k_packmem<<<2048, 256>>>(mem);
    k_packraw<<<2048, 256>>>(raw);
    k_msgT<<<2 * NB, 512, SMEM_MSG>>>(tw, tb, Ws, bs, Wd, bd, src, dst, tt, lu);
    k_gi2 <<<NB, 384, GI_SMEM>>>(Wih, bih);
    k_out2<<<NB, 384, OUT_SMEM>>>(Whh, bhh, mem, out);
    if (out_size >= NN * DD + NN)
        k_lu<<<(NN + 255) / 256, 256>>>(out);
}

// round 12
// speedup vs baseline: 2.8891x; 1.2547x over previous
#include <cuda_runtime.h>
#include <cuda_bf16.h>
#include <cuda_fp16.h>
#include <math.h>
#include <stdint.h>

#define NN 131072
#define EE 262144
#define DD 128
#define RR 128
#define NB 148
#define GOUT 384

#define TWO_PI_C1 6.2831854820251465f
#define TWO_PI_C2 (-1.7484556e-7f)
#define INV_2PI   0.15915494309189535f

// ---- k_msgT smem layout: single fp16 X ----
#define MXW 212                        // X row stride words (mod32=20 -> conflict-free)
#define MXROW (MXW * 4)
#define M_XH 0                         // 64*848 = 54272
#define SMEM_MSG 54272
#define M_STG M_XH                     // stage overlays xh (64*132*4 = 33792)

// ---- GRU smem layout (proven) ----
#define GWLW 68
#define GXW 72
#define GSTG 388
#define GI_WLO 0
#define GI_XHI 104448
#define GI_XLO (GI_XHI + 9216)
#define GI_STG (GI_XLO + 9216)
#define GI_SMEM (GI_STG + 49664)
#define OUT_MRAW GI_SMEM
#define OUT_SMEM (OUT_MRAW + 16896)

// -------- device scratch --------
__device__ float g_sums[(size_t)NN * DD];
__device__ float g_cnt[NN];
__device__ int   g_tmax[NN];
__device__ uint2 g_gih[(size_t)NN * 96];            // gi in fp16
__device__ uint4 g_wpk[2 * 8 * 26 * 32];            // W fp16-lo mma fragments
__device__ uint32_t g_memh[(size_t)NN * 64];        // memory fp16, permuted pairs
__device__ uint32_t g_rawh[(size_t)EE * 64];        // raw fp16, permuted pairs

// ================= helpers =================
__device__ __forceinline__ void mma_bf(float* c,
                                       uint32_t a0, uint32_t a1, uint32_t a2, uint32_t a3,
                                       uint32_t b0, uint32_t b1) {
    asm volatile("mma.sync.aligned.m16n8k16.row.col.f32.bf16.bf16.f32 "
        "{%0,%1,%2,%3}, {%4,%5,%6,%7}, {%8,%9}, {%0,%1,%2,%3};"
        : "+f"(c[0]), "+f"(c[1]), "+f"(c[2]), "+f"(c[3])
        : "r"(a0), "r"(a1), "r"(a2), "r"(a3), "r"(b0), "r"(b1));
}
__device__ __forceinline__ void mma_h(float* c,
                                      uint32_t a0, uint32_t a1, uint32_t a2, uint32_t a3,
                                      uint32_t b0, uint32_t b1) {
    asm volatile("mma.sync.aligned.m16n8k16.row.col.f32.f16.f16.f32 "
        "{%0,%1,%2,%3}, {%4,%5,%6,%7}, {%8,%9}, {%0,%1,%2,%3};"
        : "+f"(c[0]), "+f"(c[1]), "+f"(c[2]), "+f"(c[3])
        : "r"(a0), "r"(a1), "r"(a2), "r"(a3), "r"(b0), "r"(b1));
}
__device__ __forceinline__ uint32_t bfhi(float2 p) {
    __nv_bfloat162 h = __floats2bfloat162_rn(p.x, p.y);
    return *reinterpret_cast<uint32_t*>(&h);
}
__device__ __forceinline__ void bfsplit(float x, float y, uint32_t& hi, uint32_t& lo) {
    __nv_bfloat162 h = __floats2bfloat162_rn(x, y);
    float rx = x - __bfloat162float(h.x);
    float ry = y - __bfloat162float(h.y);
    __nv_bfloat162 l = __floats2bfloat162_rn(rx, ry);
    hi = *reinterpret_cast<uint32_t*>(&h);
    lo = *reinterpret_cast<uint32_t*>(&l);
}
__device__ __forceinline__ void split4(float4 v, uint2& hi, uint2& lo) {
    bfsplit(v.x, v.y, hi.x, lo.x);
    bfsplit(v.z, v.w, hi.y, lo.y);
}
__device__ __forceinline__ uint32_t hpack(float2 p) {
    __half2 h = __floats2half2_rn(p.x, p.y);
    return *reinterpret_cast<uint32_t*>(&h);
}
__device__ __forceinline__ void hsplit(float2 p, uint32_t& hi, uint32_t& lo) {
    __half2 h = __floats2half2_rn(p.x, p.y);
    float rx = p.x - __half2float(__low2half(h));
    float ry = p.y - __half2float(__high2half(h));
    __half2 l = __floats2half2_rn(rx, ry);
    hi = *reinterpret_cast<uint32_t*>(&h);
    lo = *reinterpret_cast<uint32_t*>(&l);
}
__device__ __forceinline__ float cos_exact(float arg) {
    float k = rintf(__fmul_rn(arg, INV_2PI));
    float r = fmaf(-k, TWO_PI_C1, arg);
    r = fmaf(-k, TWO_PI_C2, r);
    return cosf(r);
}
__device__ __forceinline__ int permslot(int p) {
    int kk = p >> 3, pi = p & 7;
    return kk * 8 + ((pi < 4) ? 2 * pi : 2 * (pi - 4) + 1);
}

// ============================================================
__global__ void k_init() {
    size_t i = (size_t)blockIdx.x * blockDim.x + threadIdx.x;
    size_t stride = (size_t)gridDim.x * blockDim.x;
    float4* s4 = (float4*)g_sums;
    for (size_t idx = i; idx < (size_t)NN * DD / 4; idx += stride)
        s4[idx] = make_float4(0.f, 0.f, 0.f, 0.f);
    for (size_t idx = i; idx < NN; idx += stride) { g_cnt[idx] = 0.f; g_tmax[idx] = 0; }
}

// ============================================================
// Prepack memory + raw into fp16 permuted word arrays.
// ============================================================
__global__ void k_packmem(const float* __restrict__ mem) {
    size_t i = (size_t)blockIdx.x * blockDim.x + threadIdx.x;
    size_t stride = (size_t)gridDim.x * blockDim.x;
    for (size_t idx = i; idx < (size_t)NN * 64; idx += stride) {
        size_t n = idx >> 6; int p = (int)(idx & 63);
        float2 v = *(const float2*)(mem + n * 128 + 2 * p);
        g_memh[n * 64 + permslot(p)] = hpack(v);
    }
}
__global__ void k_packraw(const float* __restrict__ raw) {
    size_t i = (size_t)blockIdx.x * blockDim.x + threadIdx.x;
    size_t stride = (size_t)gridDim.x * blockDim.x;
    for (size_t idx = i; idx < (size_t)EE * 64; idx += stride) {
        size_t e = idx >> 6; int p = (int)(idx & 63);
        float2 v = *(const float2*)(raw + e * 128 + 2 * p);
        g_rawh[e * 64 + permslot(p)] = hpack(v);
    }
}

// ============================================================
// Prepack W fp16-lo mma A-fragments
// ============================================================
__global__ void k_pack(const float* __restrict__ Ws, const float* __restrict__ Wd) {
    int lane = threadIdx.x;
    int b = blockIdx.x;
    int side = b / 208;
    int rem = b - side * 208;
    int rg = rem / 26, kg = rem - (rem / 26) * 26;
    const float* W = side ? Wd : Ws;
    int g = lane >> 2, tig = lane & 3;
    int r0 = rg * 16;
    int rows[2] = {r0 + g, r0 + g + 8};
    int cols[2] = {kg * 16 + 2 * tig, kg * 16 + 8 + 2 * tig};
    uint32_t w[4];
    #pragma unroll
    for (int cc = 0; cc < 2; cc++)
        #pragma unroll
        for (int rr = 0; rr < 2; rr++) {
            float2 v = *(const float2*)(W + (size_t)rows[rr] * 416 + cols[cc]);
            uint32_t hi, lo; hsplit(v, hi, lo);
            w[cc * 2 + rr] = lo;
            (void)hi;
        }
    g_wpk[(size_t)b * 32 + lane] = make_uint4(w[0], w[1], w[2], w[3]);
}

// ============================================================
// Message MLP: mma.sync fp16 2-sweep (Whi·X + Wlo·X), single fp16 X.
// 512 threads / 16 warps, K-split warp pairs, 64-event tiles.
// ============================================================
__global__ void __launch_bounds__(512, 2) k_msgT(
    const float* __restrict__ tw,  const float* __restrict__ tb,
    const float* __restrict__ Ws,  const float* __restrict__ bs,
    const float* __restrict__ Wd,  const float* __restrict__ bd,
    const int* __restrict__ src, const int* __restrict__ dst,
    const int* __restrict__ tt,  const int* __restrict__ lu)
{
    extern __shared__ char smem[];
    uint32_t* xh = (uint32_t*)(smem + M_XH);
    float* stage = (float*)(smem + M_STG);

    const int tid  = threadIdx.x;
    const int wid  = tid >> 5;
    const int lane = tid & 31;
    const int g    = lane >> 2;
    const int tig  = lane & 3;
    const int half = wid >> 3;
    const int ks   = half * 13;
    const int side = (blockIdx.x >= NB);
    const int bid  = side ? blockIdx.x - NB : blockIdx.x;
    const float* W    = side ? Wd : Ws;
    const float* bias = side ? bd : bs;
    const int r0 = (wid & 7) * 16;
    const size_t wbase = ((size_t)side * 208 + (size_t)(wid & 7) * 26) * 32 + lane;

    // Whi fp16 A-fragments (this warp's 13 k-steps)
    uint32_t whi[13][4];
    {
        const float* w0 = W + (size_t)(r0 + g) * 416 + ks * 16 + 2 * tig;
        const float* w8 = w0 + 8 * 416;
        #pragma unroll
        for (int kk = 0; kk < 13; kk++) {
            whi[kk][0] = hpack(*(const float2*)(w0 + kk * 16));
            whi[kk][1] = hpack(*(const float2*)(w8 + kk * 16));
            whi[kk][2] = hpack(*(const float2*)(w0 + kk * 16 + 8));
            whi[kk][3] = hpack(*(const float2*)(w8 + kk * 16 + 8));
        }
    }
    const float b0r = bias[r0 + g], b1r = bias[r0 + g + 8];
    const float twj = tw[lane], tbj = tb[lane];

    for (int e0 = bid * 64; e0 < EE; e0 += NB * 64) {
        // ---- gather (prepacked fp16, zero math): 64 ev x 48 uint4 ----
        #pragma unroll
        for (int it = 0; it < 6; it++) {
            int idx = tid + it * 512;
            int ev = idx / 48, c16 = idx - (idx / 48) * 48;
            int e = e0 + ev;
            int vs = src[e], vd = dst[e];
            int a = side ? vd : vs, b = side ? vs : vd;
            size_t base;
            const uint32_t* ph;
            if (c16 < 16)      { base = (size_t)a * 64 + c16 * 4;        ph = g_memh; }
            else if (c16 < 32) { base = (size_t)b * 64 + (c16 - 16) * 4; ph = g_memh; }
            else               { base = (size_t)e * 64 + (c16 - 32) * 4; ph = g_rawh; }
            *(uint4*)(xh + ev * MXW + c16 * 4) = *(const uint4*)(ph + base);
        }
        // ---- time encoding (fp32-only Cody-Waite, fp16 store) ----
        #pragma unroll
        for (int z = 0; z < 4; z++) {
            int ev = wid + z * 16;
            int e = e0 + ev;
            int a = side ? dst[e] : src[e];
            float trel = __fsub_rn((float)tt[e], (float)lu[a]);
            float arg  = __fadd_rn(__fmul_rn(trel, twj), tbj);
            float c = cos_exact(arg);
            int k  = 384 + lane;
            int p  = k >> 1;
            int pi = p & 7, kk = p >> 3;
            int w = kk * 8 + ((pi < 4) ? 2 * pi : 2 * (pi - 4) + 1);
            int byo = ev * MXROW + w * 4 + (k & 1) * 2;
            *(__half*)((char*)smem + M_XH + byo) = __float2half_rn(c);
        }
        __syncthreads();

        // ---- mma: 2 sweeps over this warp's 13 k-steps ----
        float acc[8][4];
        #pragma unroll
        for (int et = 0; et < 8; et++)
            acc[et][0] = acc[et][1] = acc[et][2] = acc[et][3] = 0.f;
        #pragma unroll
        for (int kk = 0; kk < 13; kk++) {
            int kg = ks + kk;
            uint4 wl = __ldg(&g_wpk[wbase + (size_t)kg * 32]);
            #pragma unroll
            for (int et = 0; et < 8; et++) {
                uint2 b = *(const uint2*)(xh + (et * 8 + g) * MXW + kg * 8 + 2 * tig);
                mma_h(acc[et], whi[kk][0], whi[kk][1], whi[kk][2], whi[kk][3], b.x, b.y);
                mma_h(acc[et], wl.x, wl.y, wl.z, wl.w, b.x, b.y);
            }
        }
        __syncthreads();   // xh free -> stage overlays

        // ---- combine K halves through stage ----
        if (half) {
            #pragma unroll
            for (int et = 0; et < 8; et++) {
                int evl = et * 8 + 2 * tig;
                stage[evl * 132 + r0 + g]           = acc[et][0];
                stage[(evl + 1) * 132 + r0 + g]     = acc[et][1];
                stage[evl * 132 + r0 + g + 8]       = acc[et][2];
                stage[(evl + 1) * 132 + r0 + g + 8] = acc[et][3];
            }
        }
        __syncthreads();
        if (!half) {
            #pragma unroll
            for (int et = 0; et < 8; et++) {
                int evl = et * 8 + 2 * tig;
                float* s0 = stage + evl * 132;
                float* s1 = stage + (evl + 1) * 132;
                s0[r0 + g]     = fmaxf(acc[et][0] + s0[r0 + g]     + b0r, 0.f);
                s1[r0 + g]     = fmaxf(acc[et][1] + s1[r0 + g]     + b0r, 0.f);
                s0[r0 + g + 8] = fmaxf(acc[et][2] + s0[r0 + g + 8] + b1r, 0.f);
                s1[r0 + g + 8] = fmaxf(acc[et][3] + s1[r0 + g + 8] + b1r, 0.f);
            }
        }
        __syncthreads();

        // ---- scatter float4 atomics ----
        #pragma unroll
        for (int it = 0; it < 4; it++) {
            int idx = tid + it * 512;
            int ev = idx >> 5, q = idx & 31;
            int e = e0 + ev;
            int key = side ? dst[e] : src[e];
            float4 v = *(const float4*)(stage + ev * 132 + q * 4);
            atomicAdd((float4*)&g_sums[(size_t)key * DD + q * 4], v);
        }
        if (tid < 64) {
            int e = e0 + tid;
            int key = side ? dst[e] : src[e];
            atomicAdd(&g_cnt[key], 1.0f);
            atomicMax(&g_tmax[key], tt[e]);
        }
        __syncthreads();
    }
}

// ============================================================
// gi = aggr @ W_ih^T + b_ih via mma.sync -> fp16 g_gih (proven)
// ============================================================
__global__ void __launch_bounds__(384, 1) k_gi2(
    const float* __restrict__ Wih, const float* __restrict__ bih)
{
    extern __shared__ char smem[];
    uint32_t* wlo = (uint32_t*)(smem + GI_WLO);
    uint32_t* xhi = (uint32_t*)(smem + GI_XHI);
    uint32_t* xlo = (uint32_t*)(smem + GI_XLO);
    float* stage  = (float*)(smem + GI_STG);

    const int tid = threadIdx.x;
    const int wid = tid >> 5;
    const int lane = tid & 31;
    const int g = lane >> 2, tig = lane & 3;

    for (int idx = tid; idx < GOUT * 32; idx += 384) {
        int r = idx >> 5, c4 = idx & 31;
        float4 v = ((const float4*)Wih)[idx];
        uint2 hi, lo; split4(v, hi, lo);
        *(uint2*)((char*)smem + GI_WLO + (size_t)r * (GWLW * 4) + c4 * 8) = lo;
        (void)hi;
    }
    uint32_t whi[2][8][4];
    float bv[2][2];
    #pragma unroll
    for (int rt = 0; rt < 2; rt++) {
        int r = wid * 32 + rt * 16 + g;
        const float* w0 = Wih + (size_t)r * 128 + 2 * tig;
        const float* w8 = w0 + 8 * 128;
        #pragma unroll
        for (int kk = 0; kk < 8; kk++) {
            whi[rt][kk][0] = bfhi(*(const float2*)(w0 + kk * 16));
            whi[rt][kk][1] = bfhi(*(const float2*)(w8 + kk * 16));
            whi[rt][kk][2] = bfhi(*(const float2*)(w0 + kk * 16 + 8));
            whi[rt][kk][3] = bfhi(*(const float2*)(w8 + kk * 16 + 8));
        }
        bv[rt][0] = bih[r]; bv[rt][1] = bih[r + 8];
    }
    __syncthreads();

    for (int n0 = blockIdx.x * 32; n0 < NN; n0 += gridDim.x * 32) {
        for (int idx = tid; idx < 32 * 32; idx += 384) {
            int n = idx >> 5, c4 = idx & 31;
            float4 v = ((const float4*)g_sums)[(size_t)(n0 + n) * 32 + c4];
            float inv = 1.0f / fmaxf(g_cnt[n0 + n], 1.0f);
            v.x *= inv; v.y *= inv; v.z *= inv; v.w *= inv;
            uint2 hi, lo; split4(v, hi, lo);
            int q = c4 & 3;
            int w = (c4 >> 2) * 8 + (q >> 1) + (q & 1) * 4;
            uint32_t* xhp = xhi + n * GXW + w;
            uint32_t* xlp = xlo + n * GXW + w;
            xhp[0] = hi.x; xhp[2] = hi.y;
            xlp[0] = lo.x; xlp[2] = lo.y;
        }
        __syncthreads();

        float acc[2][4][4];
        #pragma unroll
        for (int rt = 0; rt < 2; rt++)
            #pragma unroll
            for (int et = 0; et < 4; et++)
                acc[rt][et][0] = acc[rt][et][1] = acc[rt][et][2] = acc[rt][et][3] = 0.f;
        #pragma unroll
        for (int kk = 0; kk < 8; kk++) {
            uint2 bh[4], bl[4];
            #pragma unroll
            for (int et = 0; et < 4; et++) {
                bh[et] = *(const uint2*)(xhi + (et * 8 + g) * GXW + kk * 8 + 2 * tig);
                bl[et] = *(const uint2*)(xlo + (et * 8 + g) * GXW + kk * 8 + 2 * tig);
            }
            #pragma unroll
            for (int rt = 0; rt < 2; rt++) {
                int r = wid * 32 + rt * 16 + g;
                uint32_t a0 = wlo[r * GWLW + kk * 8 + tig];
                uint32_t a1 = wlo[(r + 8) * GWLW + kk * 8 + tig];
                uint32_t a2 = wlo[r * GWLW + kk * 8 + tig + 4];
                uint32_t a3 = wlo[(r + 8) * GWLW + kk * 8 + tig + 4];
                #pragma unroll
                for (int et = 0; et < 4; et++) {
                    mma_bf(acc[rt][et], whi[rt][kk][0], whi[rt][kk][1], whi[rt][kk][2], whi[rt][kk][3], bh[et].x, bh[et].y);
                    mma_bf(acc[rt][et], a0, a1, a2, a3, bh[et].x, bh[et].y);
                    mma_bf(acc[rt][et], whi[rt][kk][0], whi[rt][kk][1], whi[rt][kk][2], whi[rt][kk][3], bl[et].x, bl[et].y);
                }
            }
        }
        #pragma unroll
        for (int rt = 0; rt < 2; rt++) {
            int r = wid * 32 + rt * 16 + g;
            #pragma unroll
            for (int et = 0; et < 4; et++) {
                int nl = et * 8 + 2 * tig;
                stage[nl * GSTG + r]           = acc[rt][et][0] + bv[rt][0];
                stage[(nl + 1) * GSTG + r]     = acc[rt][et][1] + bv[rt][0];
                stage[nl * GSTG + r + 8]       = acc[rt][et][2] + bv[rt][1];
                stage[(nl + 1) * GSTG + r + 8] = acc[rt][et][3] + bv[rt][1];
            }
        }
        __syncthreads();
        for (int idx = tid; idx < 32 * 96; idx += 384) {
            int n = idx / 96, c4 = idx - (idx / 96) * 96;
            float4 v = *(const float4*)(stage + n * GSTG + c4 * 4);
            __half2 h0 = __floats2half2_rn(v.x, v.y);
            __half2 h1 = __floats2half2_rn(v.z, v.w);
            uint2 u;
            u.x = *reinterpret_cast<uint32_t*>(&h0);
            u.y = *reinterpret_cast<uint32_t*>(&h1);
            g_gih[(size_t)(n0 + n) * 96 + c4] = u;
        }
        __syncthreads();
    }
}

// ============================================================
// gh = mem @ W_hh^T + b_hh via mma.sync + fused GRU combine (proven)
// ============================================================
__global__ void __launch_bounds__(384, 1) k_out2(
    const float* __restrict__ Whh, const float* __restrict__ bhh,
    const float* __restrict__ mem, float* __restrict__ out)
{
    extern __shared__ char smem[];
    uint32_t* wlo = (uint32_t*)(smem + GI_WLO);
    uint32_t* xhi = (uint32_t*)(smem + GI_XHI);
    uint32_t* xlo = (uint32_t*)(smem + GI_XLO);
    float* stage  = (float*)(smem + GI_STG);
    float* mraw   = (float*)(smem + OUT_MRAW);

    const int tid = threadIdx.x;
    const int wid = tid >> 5;
    const int lane = tid & 31;
    const int g = lane >> 2, tig = lane & 3;

    for (int idx = tid; idx < GOUT * 32; idx += 384) {
        int r = idx >> 5, c4 = idx & 31;
        float4 v = ((const float4*)Whh)[idx];
        uint2 hi, lo; split4(v, hi, lo);
        *(uint2*)((char*)smem + GI_WLO + (size_t)r * (GWLW * 4) + c4 * 8) = lo;
        (void)hi;
    }
    uint32_t whi[2][8][4];
    float bv[2][2];
    #pragma unroll
    for (int rt = 0; rt < 2; rt++) {
        int r = wid * 32 + rt * 16 + g;
        const float* w0 = Whh + (size_t)r * 128 + 2 * tig;
        const float* w8 = w0 + 8 * 128;
        #pragma unroll
        for (int kk = 0; kk < 8; kk++) {
            whi[rt][kk][0] = bfhi(*(const float2*)(w0 + kk * 16));
            whi[rt][kk][1] = bfhi(*(const float2*)(w8 + kk * 16));
            whi[rt][kk][2] = bfhi(*(const float2*)(w0 + kk * 16 + 8));
            whi[rt][kk][3] = bfhi(*(const float2*)(w8 + kk * 16 + 8));
        }
        bv[rt][0] = bhh[r]; bv[rt][1] = bhh[r + 8];
    }
    __syncthreads();

    for (int n0 = blockIdx.x * 32; n0 < NN; n0 += gridDim.x * 32) {
        for (int idx = tid; idx < 32 * 32; idx += 384) {
            int n = idx >> 5, c4 = idx & 31;
            float4 v = ((const float4*)mem)[(size_t)(n0 + n) * 32 + c4];
            *(float4*)(mraw + n * 132 + c4 * 4) = v;
            uint2 hi, lo; split4(v, hi, lo);
            int q = c4 & 3;
            int w = (c4 >> 2) * 8 + (q >> 1) + (q & 1) * 4;
            uint32_t* xhp = xhi + n * GXW + w;
            uint32_t* xlp = xlo + n * GXW + w;
            xhp[0] = hi.x; xhp[2] = hi.y;
            xlp[0] = lo.x; xlp[2] = lo.y;
        }
        __syncthreads();

        float acc[2][4][4];
        #pragma unroll
        for (int rt = 0; rt < 2; rt++)
            #pragma unroll
            for (int et = 0; et < 4; et++)
                acc[rt][et][0] = acc[rt][et][1] = acc[rt][et][2] = acc[rt][et][3] = 0.f;
        #pragma unroll
        for (int kk = 0; kk < 8; kk++) {
            uint2 bh[4], bl[4];
            #pragma unroll
            for (int et = 0; et < 4; et++) {
                bh[et] = *(const uint2*)(xhi + (et * 8 + g) * GXW + kk * 8 + 2 * tig);
                bl[et] = *(const uint2*)(xlo + (et * 8 + g) * GXW + kk * 8 + 2 * tig);
            }
            #pragma unroll
            for (int rt = 0; rt < 2; rt++) {
                int r = wid * 32 + rt * 16 + g;
                uint32_t a0 = wlo[r * GWLW + kk * 8 + tig];
                uint32_t a1 = wlo[(r + 8) * GWLW + kk * 8 + tig];
                uint32_t a2 = wlo[r * GWLW + kk * 8 + tig + 4];
                uint32_t a3 = wlo[(r + 8) * GWLW + kk * 8 + tig + 4];
                #pragma unroll
                for (int et = 0; et < 4; et++) {
                    mma_bf(acc[rt][et], whi[rt][kk][0], whi[rt][kk][1], whi[rt][kk][2], whi[rt][kk][3], bh[et].x, bh[et].y);
                    mma_bf(acc[rt][et], a0, a1, a2, a3, bh[et].x, bh[et].y);
                    mma_bf(acc[rt][et], whi[rt][kk][0], whi[rt][kk][1], whi[rt][kk][2], whi[rt][kk][3], bl[et].x, bl[et].y);
                }
            }
        }
        #pragma unroll
        for (int rt = 0; rt < 2; rt++) {
            int r = wid * 32 + rt * 16 + g;
            #pragma unroll
            for (int et = 0; et < 4; et++) {
                int nl = et * 8 + 2 * tig;
                stage[nl * GSTG + r]           = acc[rt][et][0] + bv[rt][0];
                stage[(nl + 1) * GSTG + r]     = acc[rt][et][1] + bv[rt][0];
                stage[nl * GSTG + r + 8]       = acc[rt][et][2] + bv[rt][1];
                stage[(nl + 1) * GSTG + r + 8] = acc[rt][et][3] + bv[rt][1];
            }
        }
        __syncthreads();

        for (int idx = tid; idx < 32 * 32; idx += 384) {
            int n = idx >> 5, c4 = idx & 31;
            size_t gb = (size_t)(n0 + n) * 96 + c4;
            uint2 uir = g_gih[gb];
            uint2 uiz = g_gih[gb + 32];
            uint2 uin = g_gih[gb + 64];
            float2 ir01 = __half22float2(*reinterpret_cast<__half2*>(&uir.x));
            float2 ir23 = __half22float2(*reinterpret_cast<__half2*>(&uir.y));
            float2 iz01 = __half22float2(*reinterpret_cast<__half2*>(&uiz.x));
            float2 iz23 = __half22float2(*reinterpret_cast<__half2*>(&uiz.y));
            float2 in01 = __half22float2(*reinterpret_cast<__half2*>(&uin.x));
            float2 in23 = __half22float2(*reinterpret_cast<__half2*>(&uin.y));
            float4 hr = *(const float4*)(stage + n * GSTG + c4 * 4);
            float4 hz = *(const float4*)(stage + n * GSTG + 128 + c4 * 4);
            float4 hn = *(const float4*)(stage + n * GSTG + 256 + c4 * 4);
            float4 m = *(const float4*)(mraw + n * 132 + c4 * 4);
            float4 o;
            { float rg = 1.f/(1.f+expf(-(ir01.x+hr.x))), zg = 1.f/(1.f+expf(-(iz01.x+hz.x)));
              o.x = (1.f-zg)*tanhf(in01.x+rg*hn.x) + zg*m.x; }
            { float rg = 1.f/(1.f+expf(-(ir01.y+hr.y))), zg = 1.f/(1.f+expf(-(iz01.y+hz.y)));
              o.y = (1.f-zg)*tanhf(in01.y+rg*hn.y) + zg*m.y; }
            { float rg = 1.f/(1.f+expf(-(ir23.x+hr.z))), zg = 1.f/(1.f+expf(-(iz23.x+hz.z)));
              o.z = (1.f-zg)*tanhf(in23.x+rg*hn.z) + zg*m.z; }
            { float rg = 1.f/(1.f+expf(-(ir23.y+hr.w))), zg = 1.f/(1.f+expf(-(iz23.y+hz.w)));
              o.w = (1.f-zg)*tanhf(in23.y+rg*hn.w) + zg*m.w; }
            *(float4*)(out + (size_t)(n0 + n) * DD + c4 * 4) = o;
        }
        __syncthreads();
    }
}

// ============================================================
__global__ void k_lu(float* __restrict__ out) {
    int i = blockIdx.x * blockDim.x + threadIdx.x;
    if (i < NN)
        out[(size_t)NN * DD + i] = (g_cnt[i] > 0.f) ? (float)g_tmax[i] : 0.f;
}

// ============================================================
extern "C" void kernel_launch(void* const* d_in, const int* in_sizes, int n_in,
                              void* d_out, int out_size)
{
    const float* mem = (const float*)d_in[0];
    const float* raw = (const float*)d_in[1];
    const float* tw  = (const float*)d_in[2];
    const float* tb  = (const float*)d_in[3];
    const float* Ws  = (const float*)d_in[4];
    const float* bs  = (const float*)d_in[5];
    const float* Wd  = (const float*)d_in[6];
    const float* bd  = (const float*)d_in[7];
    const float* Wih = (const float*)d_in[8];
    const float* Whh = (const float*)d_in[9];
    const float* bih = (const float*)d_in[10];
    const float* bhh = (const float*)d_in[11];
    const int* src = (const int*)d_in[12];
    const int* dst = (const int*)d_in[13];
    const int* tt  = (const int*)d_in[14];
    const int* lu  = (const int*)d_in[15];
    float* out = (float*)d_out;

    cudaFuncSetAttribute(k_msgT, cudaFuncAttributeMaxDynamicSharedMemorySize, SMEM_MSG);
    cudaFuncSetAttribute(k_gi2,  cudaFuncAttributeMaxDynamicSharedMemorySize, GI_SMEM);
    cudaFuncSetAttribute(k_out2, cudaFuncAttributeMaxDynamicSharedMemorySize, OUT_SMEM);

    k_init<<<2048, 256>>>();
    k_pack<<<416, 32>>>(Ws, Wd);
    k_packmem<<<2048, 256>>>(mem);
    k_packraw<<<2048, 256>>>(raw);
    k_msgT<<<2 * NB, 512, SMEM_MSG>>>(tw, tb, Ws, bs, Wd, bd, src, dst, tt, lu);
    k_gi2 <<<NB, 384, GI_SMEM>>>(Wih, bih);
    k_out2<<<NB, 384, OUT_SMEM>>>(Whh, bhh, mem, out);
    if (out_size >= NN * DD + NN)
        k_lu<<<(NN + 255) / 256, 256>>>(out);
}

// round 13
// speedup vs baseline: 3.2886x; 1.1383x over previous
#include <cuda_runtime.h>
#include <cuda_bf16.h>
#include <cuda_fp16.h>
#include <math.h>
#include <stdint.h>

#define NN 131072
#define EE 262144
#define DD 128
#define RR 128
#define NB 148
#define GOUT 384

#define TWO_PI_C1 6.2831854820251465f
#define TWO_PI_C2 (-1.7484556e-7f)
#define INV_2PI   0.15915494309189535f

// ---- k_msgT smem: single fp16 X ----
#define MXW 212
#define MXROW (MXW * 4)
#define M_XH 0
#define SMEM_MSG 54272
#define M_STG M_XH

// ---- GRU smem: xh + stage only ----
#define GXW 72
#define GSTG 388
#define G_XH 0                          // 32*72*4 = 9216
#define G_STG 9216                      // 32*388*4 = 49664
#define SMEM_GRU (G_STG + 49664)        // 58880 -> 2 CTAs/SM

// -------- device scratch --------
__device__ float g_sums[(size_t)NN * DD];
__device__ float g_cnt[NN];
__device__ int   g_tmax[NN];
__device__ uint2 g_gih[(size_t)NN * 96];          // gi in fp16
__device__ uint4 g_wph[2 * 8 * 26 * 32];          // msg W fp16-hi fragments
__device__ uint4 g_wpk[2 * 8 * 26 * 32];          // msg W fp16-lo fragments
__device__ uint4 g_gwh[2 * 24 * 8 * 32];          // GRU W fp16-hi fragments
__device__ uint4 g_gwl[2 * 24 * 8 * 32];          // GRU W fp16-lo fragments
__device__ uint32_t g_memh[(size_t)NN * 64];      // memory fp16, permuted
__device__ uint32_t g_rawh[(size_t)EE * 64];      // raw fp16, permuted

// ================= helpers =================
__device__ __forceinline__ void mma_h(float* c,
                                      uint32_t a0, uint32_t a1, uint32_t a2, uint32_t a3,
                                      uint32_t b0, uint32_t b1) {
    asm volatile("mma.sync.aligned.m16n8k16.row.col.f32.f16.f16.f32 "
        "{%0,%1,%2,%3}, {%4,%5,%6,%7}, {%8,%9}, {%0,%1,%2,%3};"
        : "+f"(c[0]), "+f"(c[1]), "+f"(c[2]), "+f"(c[3])
        : "r"(a0), "r"(a1), "r"(a2), "r"(a3), "r"(b0), "r"(b1));
}
__device__ __forceinline__ uint32_t hpack(float x, float y) {
    __half2 h = __floats2half2_rn(x, y);
    return *reinterpret_cast<uint32_t*>(&h);
}
__device__ __forceinline__ void hsplit(float2 p, uint32_t& hi, uint32_t& lo) {
    __half2 h = __floats2half2_rn(p.x, p.y);
    float rx = p.x - __half2float(__low2half(h));
    float ry = p.y - __half2float(__high2half(h));
    __half2 l = __floats2half2_rn(rx, ry);
    hi = *reinterpret_cast<uint32_t*>(&h);
    lo = *reinterpret_cast<uint32_t*>(&l);
}
__device__ __forceinline__ float cos_exact(float arg) {
    float k = rintf(__fmul_rn(arg, INV_2PI));
    float r = fmaf(-k, TWO_PI_C1, arg);
    r = fmaf(-k, TWO_PI_C2, r);
    return cosf(r);
}
__device__ __forceinline__ int permslot(int p) {
    int kk = p >> 3, pi = p & 7;
    return kk * 8 + ((pi < 4) ? 2 * pi : 2 * (pi - 4) + 1);
}

// ============================================================
__global__ void k_init() {
    size_t i = (size_t)blockIdx.x * blockDim.x + threadIdx.x;
    size_t stride = (size_t)gridDim.x * blockDim.x;
    float4* s4 = (float4*)g_sums;
    for (size_t idx = i; idx < (size_t)NN * DD / 4; idx += stride)
        s4[idx] = make_float4(0.f, 0.f, 0.f, 0.f);
    for (size_t idx = i; idx < NN; idx += stride) { g_cnt[idx] = 0.f; g_tmax[idx] = 0; }
}

// ============================================================
// Prepack memory + raw into fp16 permuted word arrays.
// ============================================================
__global__ void k_packmem(const float* __restrict__ mem) {
    size_t i = (size_t)blockIdx.x * blockDim.x + threadIdx.x;
    size_t stride = (size_t)gridDim.x * blockDim.x;
    for (size_t idx = i; idx < (size_t)NN * 64; idx += stride) {
        size_t n = idx >> 6; int p = (int)(idx & 63);
        float2 v = *(const float2*)(mem + n * 128 + 2 * p);
        g_memh[n * 64 + permslot(p)] = hpack(v.x, v.y);
    }
}
__global__ void k_packraw(const float* __restrict__ raw) {
    size_t i = (size_t)blockIdx.x * blockDim.x + threadIdx.x;
    size_t stride = (size_t)gridDim.x * blockDim.x;
    for (size_t idx = i; idx < (size_t)EE * 64; idx += stride) {
        size_t e = idx >> 6; int p = (int)(idx & 63);
        float2 v = *(const float2*)(raw + e * 128 + 2 * p);
        g_rawh[e * 64 + permslot(p)] = hpack(v.x, v.y);
    }
}

// ============================================================
// Prepack msg W fp16 hi+lo mma A-fragments
// ============================================================
__global__ void k_pack(const float* __restrict__ Ws, const float* __restrict__ Wd) {
    int lane = threadIdx.x;
    int b = blockIdx.x;                 // 0..415
    int side = b / 208;
    int rem = b - side * 208;
    int rg = rem / 26, kg = rem - (rem / 26) * 26;
    const float* W = side ? Wd : Ws;
    int g = lane >> 2, tig = lane & 3;
    int r0 = rg * 16;
    int rows[2] = {r0 + g, r0 + g + 8};
    int cols[2] = {kg * 16 + 2 * tig, kg * 16 + 8 + 2 * tig};
    uint32_t wh[4], wl[4];
    #pragma unroll
    for (int cc = 0; cc < 2; cc++)
        #pragma unroll
        for (int rr = 0; rr < 2; rr++) {
            float2 v = *(const float2*)(W + (size_t)rows[rr] * 416 + cols[cc]);
            hsplit(v, wh[cc * 2 + rr], wl[cc * 2 + rr]);
        }
    g_wph[(size_t)b * 32 + lane] = make_uint4(wh[0], wh[1], wh[2], wh[3]);
    g_wpk[(size_t)b * 32 + lane] = make_uint4(wl[0], wl[1], wl[2], wl[3]);
}

// ============================================================
// Prepack GRU W fp16 hi+lo fragments. grid = 2*24*8 blocks x 32.
// index: ((m*24 + rtile)*8 + kk)*32 + lane
// ============================================================
__global__ void k_packgru(const float* __restrict__ Wih, const float* __restrict__ Whh) {
    int lane = threadIdx.x;
    int b = blockIdx.x;                 // 0..383
    int m = b / 192;
    int rem = b - m * 192;
    int rtile = rem >> 3, kk = rem & 7;
    const float* W = m ? Whh : Wih;
    int g = lane >> 2, tig = lane & 3;
    int r0 = rtile * 16;
    int rows[2] = {r0 + g, r0 + g + 8};
    int cols[2] = {kk * 16 + 2 * tig, kk * 16 + 8 + 2 * tig};
    uint32_t wh[4], wl[4];
    #pragma unroll
    for (int cc = 0; cc < 2; cc++)
        #pragma unroll
        for (int rr = 0; rr < 2; rr++) {
            float2 v = *(const float2*)(W + (size_t)rows[rr] * 128 + cols[cc]);
            hsplit(v, wh[cc * 2 + rr], wl[cc * 2 + rr]);
        }
    g_gwh[(size_t)b * 32 + lane] = make_uint4(wh[0], wh[1], wh[2], wh[3]);
    g_gwl[(size_t)b * 32 + lane] = make_uint4(wl[0], wl[1], wl[2], wl[3]);
}

// ============================================================
// Message MLP: fp16 2-sweep, all W fragments from global (no spills).
// 512 threads / 16 warps, K-split warp pairs, 64-event tiles.
// ============================================================
__global__ void __launch_bounds__(512, 2) k_msgT(
    const float* __restrict__ tw,  const float* __restrict__ tb,
    const float* __restrict__ bs,  const float* __restrict__ bd,
    const int* __restrict__ src, const int* __restrict__ dst,
    const int* __restrict__ tt,  const int* __restrict__ lu)
{
    extern __shared__ char smem[];
    uint32_t* xh = (uint32_t*)(smem + M_XH);
    float* stage = (float*)(smem + M_STG);

    const int tid  = threadIdx.x;
    const int wid  = tid >> 5;
    const int lane = tid & 31;
    const int g    = lane >> 2;
    const int tig  = lane & 3;
    const int half = wid >> 3;
    const int ks   = half * 13;
    const int side = (blockIdx.x >= NB);
    const int bid  = side ? blockIdx.x - NB : blockIdx.x;
    const float* bias = side ? bd : bs;
    const int r0 = (wid & 7) * 16;
    const size_t wbase = ((size_t)side * 208 + (size_t)(wid & 7) * 26) * 32 + lane;

    const float b0r = bias[r0 + g], b1r = bias[r0 + g + 8];
    const float twj = tw[lane], tbj = tb[lane];

    for (int e0 = bid * 64; e0 < EE; e0 += NB * 64) {
        // ---- gather (prepacked fp16): 64 ev x 48 uint4 ----
        #pragma unroll
        for (int it = 0; it < 6; it++) {
            int idx = tid + it * 512;
            int ev = idx / 48, c16 = idx - (idx / 48) * 48;
            int e = e0 + ev;
            int vs = src[e], vd = dst[e];
            int a = side ? vd : vs, b = side ? vs : vd;
            size_t base;
            const uint32_t* ph;
            if (c16 < 16)      { base = (size_t)a * 64 + c16 * 4;        ph = g_memh; }
            else if (c16 < 32) { base = (size_t)b * 64 + (c16 - 16) * 4; ph = g_memh; }
            else               { base = (size_t)e * 64 + (c16 - 32) * 4; ph = g_rawh; }
            *(uint4*)(xh + ev * MXW + c16 * 4) = *(const uint4*)(ph + base);
        }
        // ---- time encoding ----
        #pragma unroll
        for (int z = 0; z < 4; z++) {
            int ev = wid + z * 16;
            int e = e0 + ev;
            int a = side ? dst[e] : src[e];
            float trel = __fsub_rn((float)tt[e], (float)lu[a]);
            float arg  = __fadd_rn(__fmul_rn(trel, twj), tbj);
            float c = cos_exact(arg);
            int k  = 384 + lane;
            int p  = k >> 1;
            int pi = p & 7, kk = p >> 3;
            int w = kk * 8 + ((pi < 4) ? 2 * pi : 2 * (pi - 4) + 1);
            int byo = ev * MXROW + w * 4 + (k & 1) * 2;
            *(__half*)((char*)smem + M_XH + byo) = __float2half_rn(c);
        }
        __syncthreads();

        // ---- mma: 2 sweeps, W frags streamed from global ----
        float acc[8][4];
        #pragma unroll
        for (int et = 0; et < 8; et++)
            acc[et][0] = acc[et][1] = acc[et][2] = acc[et][3] = 0.f;
        #pragma unroll 1
        for (int kk = 0; kk < 13; kk++) {
            int kg = ks + kk;
            uint4 wh = __ldg(&g_wph[wbase + (size_t)kg * 32]);
            uint4 wl = __ldg(&g_wpk[wbase + (size_t)kg * 32]);
            #pragma unroll
            for (int et = 0; et < 8; et++) {
                uint2 b = *(const uint2*)(xh + (et * 8 + g) * MXW + kg * 8 + 2 * tig);
                mma_h(acc[et], wh.x, wh.y, wh.z, wh.w, b.x, b.y);
                mma_h(acc[et], wl.x, wl.y, wl.z, wl.w, b.x, b.y);
            }
        }
        __syncthreads();   // xh free -> stage overlays

        // ---- combine K halves through stage ----
        if (half) {
            #pragma unroll
            for (int et = 0; et < 8; et++) {
                int evl = et * 8 + 2 * tig;
                stage[evl * 132 + r0 + g]           = acc[et][0];
                stage[(evl + 1) * 132 + r0 + g]     = acc[et][1];
                stage[evl * 132 + r0 + g + 8]       = acc[et][2];
                stage[(evl + 1) * 132 + r0 + g + 8] = acc[et][3];
            }
        }
        __syncthreads();
        if (!half) {
            #pragma unroll
            for (int et = 0; et < 8; et++) {
                int evl = et * 8 + 2 * tig;
                float* s0 = stage + evl * 132;
                float* s1 = stage + (evl + 1) * 132;
                s0[r0 + g]     = fmaxf(acc[et][0] + s0[r0 + g]     + b0r, 0.f);
                s1[r0 + g]     = fmaxf(acc[et][1] + s1[r0 + g]     + b0r, 0.f);
                s0[r0 + g + 8] = fmaxf(acc[et][2] + s0[r0 + g + 8] + b1r, 0.f);
                s1[r0 + g + 8] = fmaxf(acc[et][3] + s1[r0 + g + 8] + b1r, 0.f);
            }
        }
        __syncthreads();

        // ---- scatter float4 atomics ----
        #pragma unroll
        for (int it = 0; it < 4; it++) {
            int idx = tid + it * 512;
            int ev = idx >> 5, q = idx & 31;
            int e = e0 + ev;
            int key = side ? dst[e] : src[e];
            float4 v = *(const float4*)(stage + ev * 132 + q * 4);
            atomicAdd((float4*)&g_sums[(size_t)key * DD + q * 4], v);
        }
        if (tid < 64) {
            int e = e0 + tid;
            int key = side ? dst[e] : src[e];
            atomicAdd(&g_cnt[key], 1.0f);
            atomicMax(&g_tmax[key], tt[e]);
        }
        __syncthreads();
    }
}

// ============================================================
// gi = aggr @ W_ih^T + b_ih, fp16 2-sweep, W frags global, X prefetch.
// 384 thr / 12 warps; warp owns rows wid*32..+32; 32 nodes/tile.
// ============================================================
__global__ void __launch_bounds__(384, 2) k_gi3(const float* __restrict__ bih)
{
    extern __shared__ char smem[];
    uint32_t* xh = (uint32_t*)(smem + G_XH);
    float* stage = (float*)(smem + G_STG);

    const int tid = threadIdx.x;
    const int wid = tid >> 5;
    const int lane = tid & 31;
    const int g = lane >> 2, tig = lane & 3;
    const int stride = gridDim.x * 32;

    float bv[2][2];
    #pragma unroll
    for (int rt = 0; rt < 2; rt++) {
        bv[rt][0] = bih[wid * 32 + rt * 16 + g];
        bv[rt][1] = bih[wid * 32 + rt * 16 + g + 8];
    }

    float4 pv[3]; float pc[3];
#define PREF_GI(N0) do {                                                   \
    _Pragma("unroll")                                                      \
    for (int it = 0; it < 3; it++) {                                       \
        int idx = tid + it * 384;                                          \
        if (idx < 1024) {                                                  \
            int n = (N0) + (idx >> 5);                                     \
            pv[it] = ((const float4*)g_sums)[(size_t)n * 32 + (idx & 31)]; \
            pc[it] = g_cnt[n];                                             \
        }                                                                  \
    }                                                                      \
} while (0)

    PREF_GI(blockIdx.x * 32);
    for (int n0 = blockIdx.x * 32; n0 < NN; n0 += stride) {
        // ---- STS prefetched X (fp16 single, permuted) ----
        #pragma unroll
        for (int it = 0; it < 3; it++) {
            int idx = tid + it * 384;
            if (idx < 1024) {
                int n = idx >> 5, c4 = idx & 31;
                float inv = 1.0f / fmaxf(pc[it], 1.0f);
                float4 v = pv[it];
                int q = c4 & 3;
                int w = (c4 >> 2) * 8 + (q >> 1) + (q & 1) * 4;
                xh[n * GXW + w]     = hpack(v.x * inv, v.y * inv);
                xh[n * GXW + w + 2] = hpack(v.z * inv, v.w * inv);
            }
        }
        __syncthreads();
        if (n0 + stride < NN) PREF_GI(n0 + stride);

        // ---- mma: 2 sweeps x 8 k-steps ----
        float acc[2][4][4];
        #pragma unroll
        for (int rt = 0; rt < 2; rt++)
            #pragma unroll
            for (int et = 0; et < 4; et++)
                acc[rt][et][0] = acc[rt][et][1] = acc[rt][et][2] = acc[rt][et][3] = 0.f;
        #pragma unroll 1
        for (int kk = 0; kk < 8; kk++) {
            uint2 b[4];
            #pragma unroll
            for (int et = 0; et < 4; et++)
                b[et] = *(const uint2*)(xh + (et * 8 + g) * GXW + kk * 8 + 2 * tig);
            #pragma unroll
            for (int rt = 0; rt < 2; rt++) {
                size_t fb = (((size_t)(wid * 2 + rt)) * 8 + kk) * 32 + lane;
                uint4 wh = __ldg(&g_gwh[fb]);
                uint4 wl = __ldg(&g_gwl[fb]);
                #pragma unroll
                for (int et = 0; et < 4; et++) {
                    mma_h(acc[rt][et], wh.x, wh.y, wh.z, wh.w, b[et].x, b[et].y);
                    mma_h(acc[rt][et], wl.x, wl.y, wl.z, wl.w, b[et].x, b[et].y);
                }
            }
        }
        #pragma unroll
        for (int rt = 0; rt < 2; rt++) {
            int r = wid * 32 + rt * 16 + g;
            #pragma unroll
            for (int et = 0; et < 4; et++) {
                int nl = et * 8 + 2 * tig;
                stage[nl * GSTG + r]           = acc[rt][et][0] + bv[rt][0];
                stage[(nl + 1) * GSTG + r]     = acc[rt][et][1] + bv[rt][0];
                stage[nl * GSTG + r + 8]       = acc[rt][et][2] + bv[rt][1];
                stage[(nl + 1) * GSTG + r + 8] = acc[rt][et][3] + bv[rt][1];
            }
        }
        __syncthreads();

        // ---- write gi fp16 ----
        #pragma unroll
        for (int it = 0; it < 8; it++) {
            int idx = tid + it * 384;
            int n = idx / 96, c4 = idx - (idx / 96) * 96;
            float4 v = *(const float4*)(stage + n * GSTG + c4 * 4);
            uint2 u;
            u.x = hpack(v.x, v.y);
            u.y = hpack(v.z, v.w);
            g_gih[(size_t)(n0 + n) * 96 + c4] = u;
        }
    }
#undef PREF_GI
}

// ============================================================
// gh = mem @ W_hh^T + b_hh + fused GRU combine. X from g_memh (prepacked).
// ============================================================
__global__ void __launch_bounds__(384, 2) k_out3(
    const float* __restrict__ bhh, const float* __restrict__ mem,
    float* __restrict__ out)
{
    extern __shared__ char smem[];
    uint32_t* xh = (uint32_t*)(smem + G_XH);
    float* stage = (float*)(smem + G_STG);

    const int tid = threadIdx.x;
    const int wid = tid >> 5;
    const int lane = tid & 31;
    const int g = lane >> 2, tig = lane & 3;
    const int stride = gridDim.x * 32;

    float bv[2][2];
    #pragma unroll
    for (int rt = 0; rt < 2; rt++) {
        bv[rt][0] = bhh[wid * 32 + rt * 16 + g];
        bv[rt][1] = bhh[wid * 32 + rt * 16 + g + 8];
    }

    uint4 pu[2];
#define PREF_OUT(N0) do {                                                  \
    _Pragma("unroll")                                                      \
    for (int it = 0; it < 2; it++) {                                       \
        int idx = tid + it * 384;                                          \
        if (idx < 512) {                                                   \
            int n = (N0) + (idx >> 4), c16 = idx & 15;                     \
            pu[it] = *(const uint4*)(g_memh + (size_t)n * 64 + c16 * 4);   \
        }                                                                  \
    }                                                                      \
} while (0)

    PREF_OUT(blockIdx.x * 32);
    for (int n0 = blockIdx.x * 32; n0 < NN; n0 += stride) {
        #pragma unroll
        for (int it = 0; it < 2; it++) {
            int idx = tid + it * 384;
            if (idx < 512) {
                int n = idx >> 4, c16 = idx & 15;
                *(uint4*)(xh + n * GXW + c16 * 4) = pu[it];
            }
        }
        __syncthreads();
        if (n0 + stride < NN) PREF_OUT(n0 + stride);

        float acc[2][4][4];
        #pragma unroll
        for (int rt = 0; rt < 2; rt++)
            #pragma unroll
            for (int et = 0; et < 4; et++)
                acc[rt][et][0] = acc[rt][et][1] = acc[rt][et][2] = acc[rt][et][3] = 0.f;
        #pragma unroll 1
        for (int kk = 0; kk < 8; kk++) {
            uint2 b[4];
            #pragma unroll
            for (int et = 0; et < 4; et++)
                b[et] = *(const uint2*)(xh + (et * 8 + g) * GXW + kk * 8 + 2 * tig);
            #pragma unroll
            for (int rt = 0; rt < 2; rt++) {
                size_t fb = (((size_t)24 + (wid * 2 + rt)) * 8 + kk) * 32 + lane;
                uint4 wh = __ldg(&g_gwh[fb]);
                uint4 wl = __ldg(&g_gwl[fb]);
                #pragma unroll
                for (int et = 0; et < 4; et++) {
                    mma_h(acc[rt][et], wh.x, wh.y, wh.z, wh.w, b[et].x, b[et].y);
                    mma_h(acc[rt][et], wl.x, wl.y, wl.z, wl.w, b[et].x, b[et].y);
                }
            }
        }
        #pragma unroll
        for (int rt = 0; rt < 2; rt++) {
            int r = wid * 32 + rt * 16 + g;
            #pragma unroll
            for (int et = 0; et < 4; et++) {
                int nl = et * 8 + 2 * tig;
                stage[nl * GSTG + r]           = acc[rt][et][0] + bv[rt][0];
                stage[(nl + 1) * GSTG + r]     = acc[rt][et][1] + bv[rt][0];
                stage[nl * GSTG + r + 8]       = acc[rt][et][2] + bv[rt][1];
                stage[(nl + 1) * GSTG + r + 8] = acc[rt][et][3] + bv[rt][1];
            }
        }
        __syncthreads();

        // ---- fused GRU combine (mem fp32 direct from global) ----
        #pragma unroll
        for (int it = 0; it < 3; it++) {
            int idx = tid + it * 384;
            if (idx < 1024) {
                int n = idx >> 5, c4 = idx & 31;
                size_t gb = (size_t)(n0 + n) * 96 + c4;
                uint2 uir = g_gih[gb];
                uint2 uiz = g_gih[gb + 32];
                uint2 uin = g_gih[gb + 64];
                float2 ir01 = __half22float2(*reinterpret_cast<__half2*>(&uir.x));
                float2 ir23 = __half22float2(*reinterpret_cast<__half2*>(&uir.y));
                float2 iz01 = __half22float2(*reinterpret_cast<__half2*>(&uiz.x));
                float2 iz23 = __half22float2(*reinterpret_cast<__half2*>(&uiz.y));
                float2 in01 = __half22float2(*reinterpret_cast<__half2*>(&uin.x));
                float2 in23 = __half22float2(*reinterpret_cast<__half2*>(&uin.y));
                float4 hr = *(const float4*)(stage + n * GSTG + c4 * 4);
                float4 hz = *(const float4*)(stage + n * GSTG + 128 + c4 * 4);
                float4 hn = *(const float4*)(stage + n * GSTG + 256 + c4 * 4);
                float4 m = ((const float4*)mem)[(size_t)(n0 + n) * 32 + c4];
                float4 o;
                { float rg = 1.f/(1.f+expf(-(ir01.x+hr.x))), zg = 1.f/(1.f+expf(-(iz01.x+hz.x)));
                  o.x = (1.f-zg)*tanhf(in01.x+rg*hn.x) + zg*m.x; }
                { float rg = 1.f/(1.f+expf(-(ir01.y+hr.y))), zg = 1.f/(1.f+expf(-(iz01.y+hz.y)));
                  o.y = (1.f-zg)*tanhf(in01.y+rg*hn.y) + zg*m.y; }
                { float rg = 1.f/(1.f+expf(-(ir23.x+hr.z))), zg = 1.f/(1.f+expf(-(iz23.x+hz.z)));
                  o.z = (1.f-zg)*tanhf(in23.x+rg*hn.z) + zg*m.z; }
                { float rg = 1.f/(1.f+expf(-(ir23.y+hr.w))), zg = 1.f/(1.f+expf(-(iz23.y+hz.w)));
                  o.w = (1.f-zg)*tanhf(in23.y+rg*hn.w) + zg*m.w; }
                ((float4*)out)[(size_t)(n0 + n) * 32 + c4] = o;
            }
        }
    }
#undef PREF_OUT
}

// ============================================================
__global__ void k_lu(float* __restrict__ out) {
    int i = blockIdx.x * blockDim.x + threadIdx.x;
    if (i < NN)
        out[(size_t)NN * DD + i] = (g_cnt[i] > 0.f) ? (float)g_tmax[i] : 0.f;
}

// ============================================================
extern "C" void kernel_launch(void* const* d_in, const int* in_sizes, int n_in,
                              void* d_out, int out_size)
{
    const float* mem = (const float*)d_in[0];
    const float* raw = (const float*)d_in[1];
    const float* tw  = (const float*)d_in[2];
    const float* tb  = (const float*)d_in[3];
    const float* Ws  = (const float*)d_in[4];
    const float* bs  = (const float*)d_in[5];
    const float* Wd  = (const float*)d_in[6];
    const float* bd  = (const float*)d_in[7];
    const float* Wih = (const float*)d_in[8];
    const float* Whh = (const float*)d_in[9];
    const float* bih = (const float*)d_in[10];
    const float* bhh = (const float*)d_in[11];
    const int* src = (const int*)d_in[12];
    const int* dst = (const int*)d_in[13];
    const int* tt  = (const int*)d_in[14];
    const int* lu  = (const int*)d_in[15];
    float* out = (float*)d_out;

    cudaFuncSetAttribute(k_msgT, cudaFuncAttributeMaxDynamicSharedMemorySize, SMEM_MSG);
    cudaFuncSetAttribute(k_gi3,  cudaFuncAttributeMaxDynamicSharedMemorySize, SMEM_GRU);
    cudaFuncSetAttribute(k_out3, cudaFuncAttributeMaxDynamicSharedMemorySize, SMEM_GRU);

    k_init<<<2048, 256>>>();
    k_pack<<<416, 32>>>(Ws, Wd);
    k_packgru<<<384, 32>>>(Wih, Whh);
    k_packmem<<<2048, 256>>>(mem);
    k_packraw<<<2048, 256>>>(raw);
    k_msgT<<<2 * NB, 512, SMEM_MSG>>>(tw, tb, bs, bd, src, dst, tt, lu);
    k_gi3 <<<NB, 384, SMEM_GRU>>>(bih);
    k_out3<<<NB, 384, SMEM_GRU>>>(bhh, mem, out);
    if (out_size >= NN * DD + NN)
        k_lu<<<(NN + 255) / 256, 256>>>(out);
}